// round 2
// baseline (speedup 1.0000x reference)
#include <cuda_runtime.h>
#include <math.h>

#define NIMG 64          // T*B = 16*4
#define HW   16384       // 128*128

// Scratch (allocation-free rule: __device__ globals)
__device__ float g_z [NIMG *  2 * HW];   //  8 MB: integrated+meaned input
__device__ float g_xm[NIMG * 16 * HW];   // 64 MB: head conv output
__device__ float g_h1[NIMG * 16 * HW];   // 64 MB: sq1 conv output

// ---------------------------------------------------------------------------
// K1: leaky integration over T per TC slice + mean over TC.
// z[t,b,c] = (1/5) * sum_tc S[t,tc,c],  S[t,tc] = a_tc S[t-1,tc] + (1-a_tc) x[t, tc*2+c]
// Valid because the head conv is linear and shared across TC slices.
// ---------------------------------------------------------------------------
__global__ void integrate_kernel(const float* __restrict__ x,
                                 const float* __restrict__ mtc_p,
                                 float* __restrict__ z) {
    int idx = blockIdx.x * blockDim.x + threadIdx.x;   // over B*C*HW = 4*2*16384
    if (idx >= 4 * 2 * HW) return;
    int p  = idx & (HW - 1);
    int bc = idx >> 14;
    int c  = bc & 1;
    int b  = bc >> 1;

    float mtc = *mtc_p;
    float al[5], om[5];
#pragma unroll
    for (int tc = 0; tc < 5; ++tc) {
        float tau = mtc * exp2f(0.5f * (float)(tc - 2));   // sqrt(2)^(tc-2)
        al[tc] = expf(-1.0f / tau);
        om[tc] = 1.0f - al[tc];
    }
    float s[5] = {0.f, 0.f, 0.f, 0.f, 0.f};
    for (int t = 0; t < 16; ++t) {
        float acc = 0.f;
#pragma unroll
        for (int tc = 0; tc < 5; ++tc) {
            float v = x[(size_t)((t * 4 + b) * 10 + tc * 2 + c) * HW + p];
            s[tc] = al[tc] * s[tc] + om[tc] * v;
            acc += s[tc];
        }
        z[(size_t)((t * 4 + b) * 2 + c) * HW + p] = acc * 0.2f;
    }
}

// ---------------------------------------------------------------------------
// Generic 15x15 conv, CIN -> 16 channels, pad 7, 128x128 images.
// Block: 256 threads (32x8), 32x32 output tile, per-thread 4px x 16co.
// ---------------------------------------------------------------------------
template <int CIN>
__global__ __launch_bounds__(256, 2)
void conv15_to16(const float* __restrict__ in, const float* __restrict__ w,
                 float* __restrict__ out) {
    __shared__ __align__(16) float tile[46 * 48];
    __shared__ __align__(16) float wsm[225 * 16];   // [k][co], co contiguous

    int img = blockIdx.y;
    int bx0 = (blockIdx.x & 3)  * 32;
    int by0 = (blockIdx.x >> 2) * 32;
    int tid = threadIdx.x;
    int tx  = tid & 31;
    int ty  = tid >> 5;          // 0..7

    float acc[4][16];
#pragma unroll
    for (int r = 0; r < 4; ++r)
#pragma unroll
        for (int co = 0; co < 16; ++co) acc[r][co] = 0.f;

    for (int cin = 0; cin < CIN; ++cin) {
        __syncthreads();
        const float* src = in + ((size_t)img * CIN + cin) * HW;
        for (int i = tid; i < 46 * 46; i += 256) {
            int r  = i / 46, cc = i % 46;
            int gy = by0 + r - 7, gx = bx0 + cc - 7;
            float v = 0.f;
            if (gy >= 0 && gy < 128 && gx >= 0 && gx < 128) v = src[gy * 128 + gx];
            tile[r * 48 + cc] = v;
        }
        for (int i = tid; i < 225 * 16; i += 256) {
            int k = i >> 4, co = i & 15;
            wsm[i] = w[((size_t)co * CIN + cin) * 225 + k];
        }
        __syncthreads();

#pragma unroll 1
        for (int ky = 0; ky < 15; ++ky) {
            const float* trow = &tile[(ty + ky) * 48 + tx];
#pragma unroll
            for (int kx = 0; kx < 15; ++kx) {
                float in0 = trow[kx];
                float in1 = trow[kx +  8 * 48];
                float in2 = trow[kx + 16 * 48];
                float in3 = trow[kx + 24 * 48];
                const float4* wp = (const float4*)&wsm[(ky * 15 + kx) * 16];
#pragma unroll
                for (int q = 0; q < 4; ++q) {
                    float4 wv = wp[q];
                    acc[0][4*q+0] += in0 * wv.x; acc[0][4*q+1] += in0 * wv.y;
                    acc[0][4*q+2] += in0 * wv.z; acc[0][4*q+3] += in0 * wv.w;
                    acc[1][4*q+0] += in1 * wv.x; acc[1][4*q+1] += in1 * wv.y;
                    acc[1][4*q+2] += in1 * wv.z; acc[1][4*q+3] += in1 * wv.w;
                    acc[2][4*q+0] += in2 * wv.x; acc[2][4*q+1] += in2 * wv.y;
                    acc[2][4*q+2] += in2 * wv.z; acc[2][4*q+3] += in2 * wv.w;
                    acc[3][4*q+0] += in3 * wv.x; acc[3][4*q+1] += in3 * wv.y;
                    acc[3][4*q+2] += in3 * wv.z; acc[3][4*q+3] += in3 * wv.w;
                }
            }
        }
    }

#pragma unroll
    for (int r = 0; r < 4; ++r) {
        int oy = by0 + ty + 8 * r;
#pragma unroll
        for (int co = 0; co < 16; ++co)
            out[((size_t)img * 16 + co) * HW + oy * 128 + bx0 + tx] = acc[r][co];
    }
}

// ---------------------------------------------------------------------------
// K4: 15x15 conv 16 -> 1, pad 7, fused with 2x2 max pool. Writes heatmaps.
// ---------------------------------------------------------------------------
__global__ __launch_bounds__(256, 2)
void conv_sq2_pool(const float* __restrict__ in, const float* __restrict__ w,
                   float* __restrict__ out) {
    __shared__ __align__(16) float tile[46 * 48];
    __shared__ float wsm[226];
    __shared__ float ctile[32 * 32];

    int img = blockIdx.y;
    int bx0 = (blockIdx.x & 3)  * 32;
    int by0 = (blockIdx.x >> 2) * 32;
    int tid = threadIdx.x;
    int tx  = tid & 31;
    int ty  = tid >> 5;

    float acc[4] = {0.f, 0.f, 0.f, 0.f};

    for (int cin = 0; cin < 16; ++cin) {
        __syncthreads();
        const float* src = in + ((size_t)img * 16 + cin) * HW;
        for (int i = tid; i < 46 * 46; i += 256) {
            int r  = i / 46, cc = i % 46;
            int gy = by0 + r - 7, gx = bx0 + cc - 7;
            float v = 0.f;
            if (gy >= 0 && gy < 128 && gx >= 0 && gx < 128) v = src[gy * 128 + gx];
            tile[r * 48 + cc] = v;
        }
        if (tid < 225) wsm[tid] = w[cin * 225 + tid];
        __syncthreads();

#pragma unroll 1
        for (int ky = 0; ky < 15; ++ky) {
            const float* trow = &tile[(ty + ky) * 48 + tx];
#pragma unroll
            for (int kx = 0; kx < 15; ++kx) {
                float wv = wsm[ky * 15 + kx];
                acc[0] += wv * trow[kx];
                acc[1] += wv * trow[kx +  8 * 48];
                acc[2] += wv * trow[kx + 16 * 48];
                acc[3] += wv * trow[kx + 24 * 48];
            }
        }
    }

    __syncthreads();
#pragma unroll
    for (int r = 0; r < 4; ++r) ctile[(ty + 8 * r) * 32 + tx] = acc[r];
    __syncthreads();

    // 2x2 max pool: 256 threads -> 16x16 pooled outputs
    int px = tid & 15, py = tid >> 4;
    float m = fmaxf(fmaxf(ctile[(2 * py) * 32 + 2 * px],     ctile[(2 * py) * 32 + 2 * px + 1]),
                    fmaxf(ctile[(2 * py + 1) * 32 + 2 * px], ctile[(2 * py + 1) * 32 + 2 * px + 1]));
    out[(size_t)img * 4096 + (by0 / 2 + py) * 64 + (bx0 / 2 + px)] = m;
}

// ---------------------------------------------------------------------------
// K5: softmax over 64x64 heatmap + soft-argmax. One block per image.
// ---------------------------------------------------------------------------
__global__ void softargmax_kernel(const float* __restrict__ heat,
                                  float* __restrict__ coords) {
    __shared__ float red[256];
    int img = blockIdx.x, tid = threadIdx.x;
    const float* h = heat + (size_t)img * 4096;

    float v[16];
    float m = -1e30f;
#pragma unroll
    for (int i = 0; i < 16; ++i) { v[i] = h[tid + 256 * i]; m = fmaxf(m, v[i]); }

    red[tid] = m; __syncthreads();
    for (int s = 128; s > 0; s >>= 1) {
        if (tid < s) red[tid] = fmaxf(red[tid], red[tid + s]);
        __syncthreads();
    }
    m = red[0]; __syncthreads();

    float se = 0.f, sx = 0.f, sy = 0.f;
#pragma unroll
    for (int i = 0; i < 16; ++i) {
        int k = tid + 256 * i;
        float e = expf(v[i] - m);
        se += e;
        sx += e * (float)(k & 63);
        sy += e * (float)(k >> 6);
    }

    red[tid] = se; __syncthreads();
    for (int s = 128; s > 0; s >>= 1) { if (tid < s) red[tid] += red[tid + s]; __syncthreads(); }
    float tot = red[0]; __syncthreads();

    red[tid] = sx; __syncthreads();
    for (int s = 128; s > 0; s >>= 1) { if (tid < s) red[tid] += red[tid + s]; __syncthreads(); }
    float totx = red[0]; __syncthreads();

    red[tid] = sy; __syncthreads();
    for (int s = 128; s > 0; s >>= 1) { if (tid < s) red[tid] += red[tid + s]; __syncthreads(); }
    float toty = red[0];

    if (tid == 0) {
        coords[img * 2 + 0] = totx / (63.0f * tot);
        coords[img * 2 + 1] = toty / (63.0f * tot);
    }
}

// ---------------------------------------------------------------------------
extern "C" void kernel_launch(void* const* d_in, const int* in_sizes, int n_in,
                              void* d_out, int out_size) {
    const float* x      = (const float*)d_in[0];  // (16,4,10,128,128)
    const float* head_w = (const float*)d_in[1];  // (16,2,15,15)
    const float* sq1_w  = (const float*)d_in[2];  // (16,16,15,15)
    const float* sq2_w  = (const float*)d_in[3];  // (1,16,15,15)
    const float* mtc    = (const float*)d_in[4];  // scalar
    float* out = (float*)d_out;

    float *zp, *xmp, *h1p;
    cudaGetSymbolAddress((void**)&zp,  g_z);
    cudaGetSymbolAddress((void**)&xmp, g_xm);
    cudaGetSymbolAddress((void**)&h1p, g_h1);

    integrate_kernel<<<512, 256>>>(x, mtc, zp);
    conv15_to16<2><<<dim3(16, NIMG), 256>>>(zp, head_w, xmp);
    conv15_to16<16><<<dim3(16, NIMG), 256>>>(xmp, sq1_w, h1p);
    conv_sq2_pool<<<dim3(16, NIMG), 256>>>(h1p, sq2_w, out);

    // coords appended after heatmaps if out buffer holds both
    if (out_size >= NIMG * 4096 + NIMG * 2) {
        softargmax_kernel<<<NIMG, 256>>>(out, out + (size_t)NIMG * 4096);
    }
}

// round 3
// speedup vs baseline: 1.2254x; 1.2254x over previous
#include <cuda_runtime.h>
#include <math.h>

#define NIMG 64          // T*B = 16*4
#define HW   16384       // 128*128
typedef unsigned long long ull;

// Scratch (allocation-free rule: __device__ globals)
__device__ float g_z [NIMG *  2 * HW];   //  8 MB: integrated+meaned input
__device__ float g_xm[NIMG * 16 * HW];   // 64 MB: head conv output
__device__ float g_h1[NIMG * 16 * HW];   // 64 MB: sq1 conv output

// ---- Blackwell packed dual-FP32 FMA ---------------------------------------
__device__ __forceinline__ void fma2(ull& d, ull a, ull b) {
    asm("fma.rn.f32x2 %0, %1, %2, %0;" : "+l"(d) : "l"(a), "l"(b));
}
__device__ __forceinline__ ull pack2(float lo, float hi) {
    ull r; asm("mov.b64 %0, {%1, %2};" : "=l"(r) : "f"(lo), "f"(hi)); return r;
}
__device__ __forceinline__ void unpack2(ull v, float& lo, float& hi) {
    asm("mov.b64 {%0, %1}, %2;" : "=f"(lo), "=f"(hi) : "l"(v));
}

// ---------------------------------------------------------------------------
// K1: leaky integration over T per TC slice + mean over TC.
// Valid because the head conv is linear and shared across TC slices.
// ---------------------------------------------------------------------------
__global__ void integrate_kernel(const float* __restrict__ x,
                                 const float* __restrict__ mtc_p,
                                 float* __restrict__ z) {
    int idx = blockIdx.x * blockDim.x + threadIdx.x;   // over B*C*HW
    if (idx >= 4 * 2 * HW) return;
    int p  = idx & (HW - 1);
    int bc = idx >> 14;
    int c  = bc & 1;
    int b  = bc >> 1;

    float mtc = *mtc_p;
    float al[5], om[5];
#pragma unroll
    for (int tc = 0; tc < 5; ++tc) {
        float tau = mtc * exp2f(0.5f * (float)(tc - 2));
        al[tc] = expf(-1.0f / tau);
        om[tc] = 1.0f - al[tc];
    }
    float s[5] = {0.f, 0.f, 0.f, 0.f, 0.f};
    for (int t = 0; t < 16; ++t) {
        float acc = 0.f;
#pragma unroll
        for (int tc = 0; tc < 5; ++tc) {
            float v = x[(size_t)((t * 4 + b) * 10 + tc * 2 + c) * HW + p];
            s[tc] = al[tc] * s[tc] + om[tc] * v;
            acc += s[tc];
        }
        z[(size_t)((t * 4 + b) * 2 + c) * HW + p] = acc * 0.2f;
    }
}

// ---------------------------------------------------------------------------
// Generic 15x15 conv, CIN -> 16 channels, pad 7, 128x128 images.
// Block: 256 threads (32x8), 32x32 output tile, per-thread 4px x 16co.
// Accumulators packed as 8 f32x2 pairs over output channels.
// ---------------------------------------------------------------------------
template <int CIN>
__global__ __launch_bounds__(256, 2)
void conv15_to16(const float* __restrict__ in, const float* __restrict__ w,
                 float* __restrict__ out) {
    __shared__ __align__(16) float tile[46 * 48];
    __shared__ __align__(16) float wsm[225 * 16];   // [k][co], co contiguous

    int img = blockIdx.y;
    int bx0 = (blockIdx.x & 3)  * 32;
    int by0 = (blockIdx.x >> 2) * 32;
    int tid = threadIdx.x;
    int tx  = tid & 31;
    int ty  = tid >> 5;          // 0..7

    ull acc[4][8];
#pragma unroll
    for (int r = 0; r < 4; ++r)
#pragma unroll
        for (int j = 0; j < 8; ++j) acc[r][j] = 0ull;

    for (int cin = 0; cin < CIN; ++cin) {
        __syncthreads();
        const float* src = in + ((size_t)img * CIN + cin) * HW;
        for (int i = tid; i < 46 * 46; i += 256) {
            int r  = i / 46, cc = i % 46;
            int gy = by0 + r - 7, gx = bx0 + cc - 7;
            float v = 0.f;
            if (gy >= 0 && gy < 128 && gx >= 0 && gx < 128) v = src[gy * 128 + gx];
            tile[r * 48 + cc] = v;
        }
        for (int i = tid; i < 225 * 16; i += 256) {
            int k = i >> 4, co = i & 15;
            wsm[i] = w[((size_t)co * CIN + cin) * 225 + k];
        }
        __syncthreads();

#pragma unroll 1
        for (int ky = 0; ky < 15; ++ky) {
            const float* trow = &tile[(ty + ky) * 48 + tx];
#pragma unroll
            for (int kx = 0; kx < 15; ++kx) {
                ull p0 = pack2(trow[kx],           trow[kx]);
                ull p1 = pack2(trow[kx +  8 * 48], trow[kx +  8 * 48]);
                ull p2 = pack2(trow[kx + 16 * 48], trow[kx + 16 * 48]);
                ull p3 = pack2(trow[kx + 24 * 48], trow[kx + 24 * 48]);
                const ull* wq = (const ull*)&wsm[(ky * 15 + kx) * 16];
#pragma unroll
                for (int j = 0; j < 8; ++j) {
                    ull wv = wq[j];
                    fma2(acc[0][j], p0, wv);
                    fma2(acc[1][j], p1, wv);
                    fma2(acc[2][j], p2, wv);
                    fma2(acc[3][j], p3, wv);
                }
            }
        }
    }

#pragma unroll
    for (int r = 0; r < 4; ++r) {
        int oy = by0 + ty + 8 * r;
#pragma unroll
        for (int j = 0; j < 8; ++j) {
            float lo, hi;
            unpack2(acc[r][j], lo, hi);
            out[((size_t)img * 16 + 2 * j)     * HW + oy * 128 + bx0 + tx] = lo;
            out[((size_t)img * 16 + 2 * j + 1) * HW + oy * 128 + bx0 + tx] = hi;
        }
    }
}

// ---------------------------------------------------------------------------
// K4: 15x15 conv 16 -> 1, pad 7, fused with 2x2 max pool.
// 4 consecutive x-outputs per thread, register sliding window, f32x2 math.
// ---------------------------------------------------------------------------
__global__ __launch_bounds__(256, 2)
void conv_sq2_pool(const float* __restrict__ in, const float* __restrict__ w,
                   float* __restrict__ out) {
    __shared__ __align__(16) float tile[46 * 48];
    __shared__ __align__(16) ull  wsm2[225];        // (w,w) duplicated pairs
    __shared__ float ctile[32 * 32];

    int img = blockIdx.y;
    int bx0 = (blockIdx.x & 3)  * 32;
    int by0 = (blockIdx.x >> 2) * 32;
    int tid = threadIdx.x;
    int tx  = tid & 7;           // x group of 4
    int ty  = tid >> 3;          // 0..31 row

    ull accA = 0ull, accB = 0ull;   // (o0,o1), (o2,o3)

    for (int cin = 0; cin < 16; ++cin) {
        __syncthreads();
        const float* src = in + ((size_t)img * 16 + cin) * HW;
        for (int i = tid; i < 46 * 46; i += 256) {
            int r  = i / 46, cc = i % 46;
            int gy = by0 + r - 7, gx = bx0 + cc - 7;
            float v = 0.f;
            if (gy >= 0 && gy < 128 && gx >= 0 && gx < 128) v = src[gy * 128 + gx];
            tile[r * 48 + cc] = v;
        }
        if (tid < 225) {
            float wv = w[cin * 225 + tid];
            wsm2[tid] = pack2(wv, wv);
        }
        __syncthreads();

#pragma unroll 1
        for (int ky = 0; ky < 15; ++ky) {
            const float4* trow = (const float4*)&tile[(ty + ky) * 48 + 4 * tx];
            float4 v0 = trow[0], v1 = trow[1], v2 = trow[2], v3 = trow[3], v4 = trow[4];
            float r[20] = {v0.x, v0.y, v0.z, v0.w, v1.x, v1.y, v1.z, v1.w,
                           v2.x, v2.y, v2.z, v2.w, v3.x, v3.y, v3.z, v3.w,
                           v4.x, v4.y, v4.z, v4.w};
            ull pr[17];
#pragma unroll
            for (int k = 0; k < 17; ++k) pr[k] = pack2(r[k], r[k + 1]);
            const ull* wrow = &wsm2[ky * 15];
#pragma unroll
            for (int kx = 0; kx < 15; ++kx) {
                ull wv = wrow[kx];
                fma2(accA, pr[kx],     wv);
                fma2(accB, pr[kx + 2], wv);
            }
        }
    }

    __syncthreads();
    {
        float o0, o1, o2, o3;
        unpack2(accA, o0, o1);
        unpack2(accB, o2, o3);
        ctile[ty * 32 + 4 * tx + 0] = o0;
        ctile[ty * 32 + 4 * tx + 1] = o1;
        ctile[ty * 32 + 4 * tx + 2] = o2;
        ctile[ty * 32 + 4 * tx + 3] = o3;
    }
    __syncthreads();

    int px = tid & 15, py = tid >> 4;
    float m = fmaxf(fmaxf(ctile[(2 * py) * 32 + 2 * px],     ctile[(2 * py) * 32 + 2 * px + 1]),
                    fmaxf(ctile[(2 * py + 1) * 32 + 2 * px], ctile[(2 * py + 1) * 32 + 2 * px + 1]));
    out[(size_t)img * 4096 + (by0 / 2 + py) * 64 + (bx0 / 2 + px)] = m;
}

// ---------------------------------------------------------------------------
// K5: softmax over 64x64 heatmap + soft-argmax. One block per image.
// ---------------------------------------------------------------------------
__global__ void softargmax_kernel(const float* __restrict__ heat,
                                  float* __restrict__ coords) {
    __shared__ float red[256];
    int img = blockIdx.x, tid = threadIdx.x;
    const float* h = heat + (size_t)img * 4096;

    float v[16];
    float m = -1e30f;
#pragma unroll
    for (int i = 0; i < 16; ++i) { v[i] = h[tid + 256 * i]; m = fmaxf(m, v[i]); }

    red[tid] = m; __syncthreads();
    for (int s = 128; s > 0; s >>= 1) {
        if (tid < s) red[tid] = fmaxf(red[tid], red[tid + s]);
        __syncthreads();
    }
    m = red[0]; __syncthreads();

    float se = 0.f, sx = 0.f, sy = 0.f;
#pragma unroll
    for (int i = 0; i < 16; ++i) {
        int k = tid + 256 * i;
        float e = expf(v[i] - m);
        se += e;
        sx += e * (float)(k & 63);
        sy += e * (float)(k >> 6);
    }

    red[tid] = se; __syncthreads();
    for (int s = 128; s > 0; s >>= 1) { if (tid < s) red[tid] += red[tid + s]; __syncthreads(); }
    float tot = red[0]; __syncthreads();

    red[tid] = sx; __syncthreads();
    for (int s = 128; s > 0; s >>= 1) { if (tid < s) red[tid] += red[tid + s]; __syncthreads(); }
    float totx = red[0]; __syncthreads();

    red[tid] = sy; __syncthreads();
    for (int s = 128; s > 0; s >>= 1) { if (tid < s) red[tid] += red[tid + s]; __syncthreads(); }
    float toty = red[0];

    if (tid == 0) {
        coords[img * 2 + 0] = totx / (63.0f * tot);
        coords[img * 2 + 1] = toty / (63.0f * tot);
    }
}

// ---------------------------------------------------------------------------
extern "C" void kernel_launch(void* const* d_in, const int* in_sizes, int n_in,
                              void* d_out, int out_size) {
    const float* x      = (const float*)d_in[0];  // (16,4,10,128,128)
    const float* head_w = (const float*)d_in[1];  // (16,2,15,15)
    const float* sq1_w  = (const float*)d_in[2];  // (16,16,15,15)
    const float* sq2_w  = (const float*)d_in[3];  // (1,16,15,15)
    const float* mtc    = (const float*)d_in[4];  // scalar
    float* out = (float*)d_out;

    float *zp, *xmp, *h1p;
    cudaGetSymbolAddress((void**)&zp,  g_z);
    cudaGetSymbolAddress((void**)&xmp, g_xm);
    cudaGetSymbolAddress((void**)&h1p, g_h1);

    integrate_kernel<<<512, 256>>>(x, mtc, zp);
    conv15_to16<2><<<dim3(16, NIMG), 256>>>(zp, head_w, xmp);
    conv15_to16<16><<<dim3(16, NIMG), 256>>>(xmp, sq1_w, h1p);
    conv_sq2_pool<<<dim3(16, NIMG), 256>>>(h1p, sq2_w, out);

    if (out_size >= NIMG * 4096 + NIMG * 2) {
        softargmax_kernel<<<NIMG, 256>>>(out, out + (size_t)NIMG * 4096);
    }
}

// round 5
// speedup vs baseline: 1.7432x; 1.4226x over previous
#include <cuda_runtime.h>
#include <cuda_bf16.h>
#include <math.h>
#include <stdint.h>

#define NIMG 64          // T*B = 16*4
#define HW   16384       // 128*128
typedef unsigned long long ull;

// Scratch (allocation-free rule: __device__ globals; zero-initialized at load)
__device__ float   g_z [NIMG *  2 * HW];                 //  8 MB integrated input
__device__ float   g_xm[NIMG * 16 * HW];                 // 64 MB head conv output
__device__ float   g_h1[NIMG * 16 * HW];                 // 64 MB sq1 conv output
__device__ uint8_t g_xs[(size_t)NIMG * 128 * 144 * 80];  // 94 MB bf16-split pixel rows
__device__ uint8_t g_ws[225 * 1024];                     // split weights per (ky,kx)

#define ROWB 11520                       // 144 px * 80 B
#define A_BYTES (18 * ROWB)              // 207360
#define B_BYTES 15360                    // 15 kx * 1024
#define SQ1_SMEM (A_BYTES + B_BYTES)     // 222720

// ---- f32x2 helpers (head / sq2 FFMA kernels) ------------------------------
__device__ __forceinline__ void fma2(ull& d, ull a, ull b) {
    asm("fma.rn.f32x2 %0, %1, %2, %0;" : "+l"(d) : "l"(a), "l"(b));
}
__device__ __forceinline__ ull pack2(float lo, float hi) {
    ull r; asm("mov.b64 %0, {%1, %2};" : "=l"(r) : "f"(lo), "f"(hi)); return r;
}
__device__ __forceinline__ void unpack2(ull v, float& lo, float& hi) {
    asm("mov.b64 {%0, %1}, %2;" : "=f"(lo), "=f"(hi) : "l"(v));
}

// ---- HMMA helpers ---------------------------------------------------------
__device__ __forceinline__ uint32_t smem_u32(const void* p) {
    uint32_t a;
    asm("{ .reg .u64 t; cvta.to.shared.u64 t, %1; cvt.u32.u64 %0, t; }" : "=r"(a) : "l"(p));
    return a;
}
__device__ __forceinline__ void ldsm4(uint32_t& r0, uint32_t& r1, uint32_t& r2,
                                      uint32_t& r3, uint32_t a) {
    asm volatile("ldmatrix.sync.aligned.m8n8.x4.shared.b16 {%0,%1,%2,%3}, [%4];"
                 : "=r"(r0), "=r"(r1), "=r"(r2), "=r"(r3) : "r"(a));
}
__device__ __forceinline__ void mma_bf16(float* d, uint32_t a0, uint32_t a1,
                                         uint32_t a2, uint32_t a3,
                                         uint32_t b0, uint32_t b1) {
    asm volatile(
        "mma.sync.aligned.m16n8k16.row.col.f32.bf16.bf16.f32 "
        "{%0,%1,%2,%3}, {%4,%5,%6,%7}, {%8,%9}, {%0,%1,%2,%3};"
        : "+f"(d[0]), "+f"(d[1]), "+f"(d[2]), "+f"(d[3])
        : "r"(a0), "r"(a1), "r"(a2), "r"(a3), "r"(b0), "r"(b1));
}

// ---------------------------------------------------------------------------
// K1: leaky integration over T per TC slice + mean over TC.
// ---------------------------------------------------------------------------
__global__ void integrate_kernel(const float* __restrict__ x,
                                 const float* __restrict__ mtc_p,
                                 float* __restrict__ z) {
    int idx = blockIdx.x * blockDim.x + threadIdx.x;
    if (idx >= 4 * 2 * HW) return;
    int p  = idx & (HW - 1);
    int bc = idx >> 14;
    int c  = bc & 1;
    int b  = bc >> 1;

    float mtc = *mtc_p;
    float al[5], om[5];
#pragma unroll
    for (int tc = 0; tc < 5; ++tc) {
        float tau = mtc * exp2f(0.5f * (float)(tc - 2));
        al[tc] = expf(-1.0f / tau);
        om[tc] = 1.0f - al[tc];
    }
    float s[5] = {0.f, 0.f, 0.f, 0.f, 0.f};
    for (int t = 0; t < 16; ++t) {
        float acc = 0.f;
#pragma unroll
        for (int tc = 0; tc < 5; ++tc) {
            float v = x[(size_t)((t * 4 + b) * 10 + tc * 2 + c) * HW + p];
            s[tc] = al[tc] * s[tc] + om[tc] * v;
            acc += s[tc];
        }
        z[(size_t)((t * 4 + b) * 2 + c) * HW + p] = acc * 0.2f;
    }
}

// ---------------------------------------------------------------------------
// K2: head conv 2->16 (FFMA f32x2 path)
// ---------------------------------------------------------------------------
template <int CIN>
__global__ __launch_bounds__(256, 2)
void conv15_to16(const float* __restrict__ in, const float* __restrict__ w,
                 float* __restrict__ out) {
    __shared__ __align__(16) float tile[46 * 48];
    __shared__ __align__(16) float wsm[225 * 16];

    int img = blockIdx.y;
    int bx0 = (blockIdx.x & 3)  * 32;
    int by0 = (blockIdx.x >> 2) * 32;
    int tid = threadIdx.x;
    int tx  = tid & 31;
    int ty  = tid >> 5;

    ull acc[4][8];
#pragma unroll
    for (int r = 0; r < 4; ++r)
#pragma unroll
        for (int j = 0; j < 8; ++j) acc[r][j] = 0ull;

    for (int cin = 0; cin < CIN; ++cin) {
        __syncthreads();
        const float* src = in + ((size_t)img * CIN + cin) * HW;
        for (int i = tid; i < 46 * 46; i += 256) {
            int r  = i / 46, cc = i % 46;
            int gy = by0 + r - 7, gx = bx0 + cc - 7;
            float v = 0.f;
            if (gy >= 0 && gy < 128 && gx >= 0 && gx < 128) v = src[gy * 128 + gx];
            tile[r * 48 + cc] = v;
        }
        for (int i = tid; i < 225 * 16; i += 256) {
            int k = i >> 4, co = i & 15;
            wsm[i] = w[((size_t)co * CIN + cin) * 225 + k];
        }
        __syncthreads();

#pragma unroll 1
        for (int ky = 0; ky < 15; ++ky) {
            const float* trow = &tile[(ty + ky) * 48 + tx];
#pragma unroll
            for (int kx = 0; kx < 15; ++kx) {
                ull p0 = pack2(trow[kx],           trow[kx]);
                ull p1 = pack2(trow[kx +  8 * 48], trow[kx +  8 * 48]);
                ull p2 = pack2(trow[kx + 16 * 48], trow[kx + 16 * 48]);
                ull p3 = pack2(trow[kx + 24 * 48], trow[kx + 24 * 48]);
                const ull* wq = (const ull*)&wsm[(ky * 15 + kx) * 16];
#pragma unroll
                for (int j = 0; j < 8; ++j) {
                    ull wv = wq[j];
                    fma2(acc[0][j], p0, wv);
                    fma2(acc[1][j], p1, wv);
                    fma2(acc[2][j], p2, wv);
                    fma2(acc[3][j], p3, wv);
                }
            }
        }
    }

#pragma unroll
    for (int r = 0; r < 4; ++r) {
        int oy = by0 + ty + 8 * r;
#pragma unroll
        for (int j = 0; j < 8; ++j) {
            float lo, hi;
            unpack2(acc[r][j], lo, hi);
            out[((size_t)img * 16 + 2 * j)     * HW + oy * 128 + bx0 + tx] = lo;
            out[((size_t)img * 16 + 2 * j + 1) * HW + oy * 128 + bx0 + tx] = hi;
        }
    }
}

// ---------------------------------------------------------------------------
// K3a: prepass — each (img,y) row becomes 144 pixel records of 80B:
// [16 bf16 hi | 16 bf16 lo | 16B pad(0)]. Staged in smem for coalesced store.
// ---------------------------------------------------------------------------
__global__ __launch_bounds__(160, 4)
void split_rows(const float* __restrict__ in, uint8_t* __restrict__ xs) {
    __shared__ __align__(16) uint8_t rowbuf[144 * 80];
    int y = blockIdx.x, img = blockIdx.y;
    int p = threadIdx.x;

    if (p < 144) {
        int x = p - 7;
        bool valid = (x >= 0 && x < 128);
        __align__(16) __nv_bfloat16 hi[16], lo[16];
#pragma unroll
        for (int c = 0; c < 16; ++c) {
            float a = valid ? in[((size_t)(img * 16 + c) * 128 + y) * 128 + x] : 0.f;
            __nv_bfloat16 h = __float2bfloat16(a);
            hi[c] = h;
            lo[c] = __float2bfloat16(a - __bfloat162float(h));
        }
        uint8_t* rb = rowbuf + p * 80;
        *(uint4*)(rb +  0) = *(const uint4*)&hi[0];
        *(uint4*)(rb + 16) = *(const uint4*)&hi[8];
        *(uint4*)(rb + 32) = *(const uint4*)&lo[0];
        *(uint4*)(rb + 48) = *(const uint4*)&lo[8];
        *(uint4*)(rb + 64) = make_uint4(0, 0, 0, 0);
    }
    __syncthreads();
    uint8_t* dst = xs + (size_t)(img * 128 + y) * ROWB;
    for (int u = threadIdx.x; u < 720; u += 160)
        *(uint4*)(dst + u * 16) = *(const uint4*)(rowbuf + u * 16);
}

// ---------------------------------------------------------------------------
// K3b: prepass — split sq1 weights into per-(ky,kx) 1KB blocks:
// [co 16][cin 16] bf16 hi at +0, lo at +512. (ky*15+kx) blocks contiguous.
// ---------------------------------------------------------------------------
__global__ void split_weights(const float* __restrict__ w, uint8_t* __restrict__ ws) {
    int kxy = blockIdx.x;            // 0..224
    int t   = threadIdx.x;           // 0..255
    int co  = t >> 4, cin = t & 15;
    int ky  = kxy / 15, kx = kxy % 15;
    float wv = w[((size_t)(co * 16 + cin) * 15 + ky) * 15 + kx];
    __nv_bfloat16 h = __float2bfloat16(wv);
    __nv_bfloat16 l = __float2bfloat16(wv - __bfloat162float(h));
    uint8_t* dst = ws + (size_t)kxy * 1024 + co * 32 + cin * 2;
    *(__nv_bfloat16*)dst         = h;
    *(__nv_bfloat16*)(dst + 512) = l;
}

// ---------------------------------------------------------------------------
// K4: sq1 conv 16->16 via warp-level HMMA (mma.sync bf16, 3-term split).
// CTA = (image, 4 output rows); warp w owns row y0+w; 8 M-tiles of 16 px.
// ---------------------------------------------------------------------------
__global__ __launch_bounds__(128, 1)
void conv_sq1_hmma(const uint8_t* __restrict__ xs, const uint8_t* __restrict__ ws,
                   float* __restrict__ out) {
    extern __shared__ __align__(16) uint8_t sm[];
    uint8_t* Asm = sm;
    uint8_t* Bsm = sm + A_BYTES;

    int tid  = threadIdx.x;
    int lane = tid & 31;
    int w    = tid >> 5;             // warp 0..3 = output row
    int grp  = blockIdx.x;           // 0..31
    int img  = blockIdx.y;           // 0..63
    int y0   = grp * 4;
    int y    = y0 + w;

    // ---- A ring: 18 input rows (y0-7 .. y0+10), zero-padded at edges ----
    const uint8_t* srcbase = xs + (size_t)img * 128 * ROWB;
    for (int u = tid; u < 18 * 720; u += 128) {
        int slot = u / 720, q = u % 720;
        int yin  = y0 - 7 + slot;
        uint4 v = make_uint4(0, 0, 0, 0);
        if (yin >= 0 && yin < 128)
            v = *(const uint4*)(srcbase + (size_t)yin * ROWB + q * 16);
        *(uint4*)(Asm + slot * ROWB + q * 16) = v;
    }

    uint32_t asm_base = smem_u32(Asm);
    uint32_t bsm_base = smem_u32(Bsm);
    int part = lane >> 3, r = lane & 7;
    // A: m0=(rows0-7,k0-7) m1=(rows8-15,k0-7) m2=(rows0-7,k8-15) m3=(rows8-15,k8-15)
    uint32_t a_off = (uint32_t)((((part & 1) << 3) + r) * 80 + ((part >> 1) << 4));
    // B: m0=(n0-7,k0-7) m1=(n0-7,k8-15) m2=(n8-15,k0-7) m3=(n8-15,k8-15)
    uint32_t b_off = (uint32_t)((((part >> 1) << 3) + r) * 32 + ((part & 1) << 4));

    float acc[8][2][4];
#pragma unroll
    for (int t = 0; t < 8; ++t)
#pragma unroll
        for (int h = 0; h < 2; ++h)
#pragma unroll
            for (int i = 0; i < 4; ++i) acc[t][h][i] = 0.f;

#pragma unroll 1
    for (int ky = 0; ky < 15; ++ky) {
        __syncthreads();                       // A ready / previous B consumed
        const uint8_t* bw = ws + (size_t)ky * B_BYTES;
        for (int u = tid; u < 960; u += 128)
            *(uint4*)(Bsm + u * 16) = *(const uint4*)(bw + u * 16);
        __syncthreads();

        uint32_t arow = asm_base + (uint32_t)((w + ky) * ROWB) + a_off;

#pragma unroll 1
        for (int kx = 0; kx < 15; ++kx) {
            uint32_t baddr = bsm_base + kx * 1024 + b_off;
            uint32_t bh0, bh1, bh2, bh3, bl0, bl1, bl2, bl3;
            ldsm4(bh0, bh1, bh2, bh3, baddr);
            ldsm4(bl0, bl1, bl2, bl3, baddr + 512);
            uint32_t abase = arow + kx * 80;
#pragma unroll
            for (int t = 0; t < 8; ++t) {
                uint32_t aaddr = abase + t * 1280;
                uint32_t ah0, ah1, ah2, ah3, al0, al1, al2, al3;
                ldsm4(ah0, ah1, ah2, ah3, aaddr);
                ldsm4(al0, al1, al2, al3, aaddr + 32);
                mma_bf16(acc[t][0], ah0, ah1, ah2, ah3, bh0, bh1);
                mma_bf16(acc[t][1], ah0, ah1, ah2, ah3, bh2, bh3);
                mma_bf16(acc[t][0], ah0, ah1, ah2, ah3, bl0, bl1);
                mma_bf16(acc[t][1], ah0, ah1, ah2, ah3, bl2, bl3);
                mma_bf16(acc[t][0], al0, al1, al2, al3, bh0, bh1);
                mma_bf16(acc[t][1], al0, al1, al2, al3, bh2, bh3);
            }
        }
    }

    // ---- epilogue: D fragment -> g_h1[img][co][y][x] ----
    int q  = lane >> 2;
    int cb = (lane & 3) * 2;
    float* ob = out + (size_t)img * 16 * HW + y * 128;
#pragma unroll
    for (int t = 0; t < 8; ++t) {
#pragma unroll
        for (int h = 0; h < 2; ++h) {
            int co = h * 8 + cb;
            int x  = t * 16 + q;
            ob[(size_t)co       * HW + x    ] = acc[t][h][0];
            ob[(size_t)(co + 1) * HW + x    ] = acc[t][h][1];
            ob[(size_t)co       * HW + x + 8] = acc[t][h][2];
            ob[(size_t)(co + 1) * HW + x + 8] = acc[t][h][3];
        }
    }
}

// ---------------------------------------------------------------------------
// K5: 15x15 conv 16 -> 1 fused with 2x2 max pool (f32x2 path)
// ---------------------------------------------------------------------------
__global__ __launch_bounds__(256, 2)
void conv_sq2_pool(const float* __restrict__ in, const float* __restrict__ w,
                   float* __restrict__ out) {
    __shared__ __align__(16) float tile[46 * 48];
    __shared__ __align__(16) ull  wsm2[225];
    __shared__ float ctile[32 * 32];

    int img = blockIdx.y;
    int bx0 = (blockIdx.x & 3)  * 32;
    int by0 = (blockIdx.x >> 2) * 32;
    int tid = threadIdx.x;
    int tx  = tid & 7;
    int ty  = tid >> 3;

    ull accA = 0ull, accB = 0ull;

    for (int cin = 0; cin < 16; ++cin) {
        __syncthreads();
        const float* src = in + ((size_t)img * 16 + cin) * HW;
        for (int i = tid; i < 46 * 46; i += 256) {
            int r  = i / 46, cc = i % 46;
            int gy = by0 + r - 7, gx = bx0 + cc - 7;
            float v = 0.f;
            if (gy >= 0 && gy < 128 && gx >= 0 && gx < 128) v = src[gy * 128 + gx];
            tile[r * 48 + cc] = v;
        }
        if (tid < 225) {
            float wv = w[cin * 225 + tid];
            wsm2[tid] = pack2(wv, wv);
        }
        __syncthreads();

#pragma unroll 1
        for (int ky = 0; ky < 15; ++ky) {
            const float4* trow = (const float4*)&tile[(ty + ky) * 48 + 4 * tx];
            float4 v0 = trow[0], v1 = trow[1], v2 = trow[2], v3 = trow[3], v4 = trow[4];
            float rr[20] = {v0.x, v0.y, v0.z, v0.w, v1.x, v1.y, v1.z, v1.w,
                            v2.x, v2.y, v2.z, v2.w, v3.x, v3.y, v3.z, v3.w,
                            v4.x, v4.y, v4.z, v4.w};
            ull pr[17];
#pragma unroll
            for (int k = 0; k < 17; ++k) pr[k] = pack2(rr[k], rr[k + 1]);
            const ull* wrow = &wsm2[ky * 15];
#pragma unroll
            for (int kx = 0; kx < 15; ++kx) {
                ull wv = wrow[kx];
                fma2(accA, pr[kx],     wv);
                fma2(accB, pr[kx + 2], wv);
            }
        }
    }

    __syncthreads();
    {
        float o0, o1, o2, o3;
        unpack2(accA, o0, o1);
        unpack2(accB, o2, o3);
        ctile[ty * 32 + 4 * tx + 0] = o0;
        ctile[ty * 32 + 4 * tx + 1] = o1;
        ctile[ty * 32 + 4 * tx + 2] = o2;
        ctile[ty * 32 + 4 * tx + 3] = o3;
    }
    __syncthreads();

    int px = tid & 15, py = tid >> 4;
    float m = fmaxf(fmaxf(ctile[(2 * py) * 32 + 2 * px],     ctile[(2 * py) * 32 + 2 * px + 1]),
                    fmaxf(ctile[(2 * py + 1) * 32 + 2 * px], ctile[(2 * py + 1) * 32 + 2 * px + 1]));
    out[(size_t)img * 4096 + (by0 / 2 + py) * 64 + (bx0 / 2 + px)] = m;
}

// ---------------------------------------------------------------------------
// K6: softmax over 64x64 heatmap + soft-argmax. One block per image.
// ---------------------------------------------------------------------------
__global__ void softargmax_kernel(const float* __restrict__ heat,
                                  float* __restrict__ coords) {
    __shared__ float red[256];
    int img = blockIdx.x, tid = threadIdx.x;
    const float* h = heat + (size_t)img * 4096;

    float v[16];
    float m = -1e30f;
#pragma unroll
    for (int i = 0; i < 16; ++i) { v[i] = h[tid + 256 * i]; m = fmaxf(m, v[i]); }

    red[tid] = m; __syncthreads();
    for (int s = 128; s > 0; s >>= 1) {
        if (tid < s) red[tid] = fmaxf(red[tid], red[tid + s]);
        __syncthreads();
    }
    m = red[0]; __syncthreads();

    float se = 0.f, sx = 0.f, sy = 0.f;
#pragma unroll
    for (int i = 0; i < 16; ++i) {
        int k = tid + 256 * i;
        float e = expf(v[i] - m);
        se += e;
        sx += e * (float)(k & 63);
        sy += e * (float)(k >> 6);
    }

    red[tid] = se; __syncthreads();
    for (int s = 128; s > 0; s >>= 1) { if (tid < s) red[tid] += red[tid + s]; __syncthreads(); }
    float tot = red[0]; __syncthreads();

    red[tid] = sx; __syncthreads();
    for (int s = 128; s > 0; s >>= 1) { if (tid < s) red[tid] += red[tid + s]; __syncthreads(); }
    float totx = red[0]; __syncthreads();

    red[tid] = sy; __syncthreads();
    for (int s = 128; s > 0; s >>= 1) { if (tid < s) red[tid] += red[tid + s]; __syncthreads(); }
    float toty = red[0];

    if (tid == 0) {
        coords[img * 2 + 0] = totx / (63.0f * tot);
        coords[img * 2 + 1] = toty / (63.0f * tot);
    }
}

// ---------------------------------------------------------------------------
extern "C" void kernel_launch(void* const* d_in, const int* in_sizes, int n_in,
                              void* d_out, int out_size) {
    const float* x      = (const float*)d_in[0];
    const float* head_w = (const float*)d_in[1];
    const float* sq1_w  = (const float*)d_in[2];
    const float* sq2_w  = (const float*)d_in[3];
    const float* mtc    = (const float*)d_in[4];
    float* out = (float*)d_out;

    float *zp, *xmp, *h1p;
    uint8_t *xsp, *wsp;
    cudaGetSymbolAddress((void**)&zp,  g_z);
    cudaGetSymbolAddress((void**)&xmp, g_xm);
    cudaGetSymbolAddress((void**)&h1p, g_h1);
    cudaGetSymbolAddress((void**)&xsp, g_xs);
    cudaGetSymbolAddress((void**)&wsp, g_ws);

    cudaFuncSetAttribute(conv_sq1_hmma,
                         cudaFuncAttributeMaxDynamicSharedMemorySize, SQ1_SMEM);

    integrate_kernel<<<512, 256>>>(x, mtc, zp);
    split_weights<<<225, 256>>>(sq1_w, wsp);
    conv15_to16<2><<<dim3(16, NIMG), 256>>>(zp, head_w, xmp);
    split_rows<<<dim3(128, NIMG), 160>>>(xmp, xsp);
    conv_sq1_hmma<<<dim3(32, NIMG), 128, SQ1_SMEM>>>(xsp, wsp, h1p);
    conv_sq2_pool<<<dim3(16, NIMG), 256>>>(h1p, sq2_w, out);

    if (out_size >= NIMG * 4096 + NIMG * 2) {
        softargmax_kernel<<<NIMG, 256>>>(out, out + (size_t)NIMG * 4096);
    }
}

// round 6
// speedup vs baseline: 1.9367x; 1.1109x over previous
#include <cuda_runtime.h>
#include <cuda_bf16.h>
#include <math.h>
#include <stdint.h>

#define NIMG 64          // T*B = 16*4
#define HW   16384       // 128*128
typedef unsigned long long ull;

// Scratch (allocation-free rule: __device__ globals; zero-initialized at load)
__device__ float   g_z [NIMG *  2 * HW];                 //  8 MB integrated input
__device__ float   g_xm[NIMG * 16 * HW];                 // 64 MB head conv output
__device__ float   g_h1[NIMG * 16 * HW];                 // 64 MB sq1 conv output
__device__ uint8_t g_xs[(size_t)NIMG * 128 * 144 * 80];  // 94 MB bf16-split pixel rows
__device__ uint8_t g_ws[225 * 1024];                     // split weights per (ky,kx)

#define ROWB 11520                       // 144 px * 80 B
#define A_BYTES (18 * ROWB)              // 207360
#define B_BYTES 15360                    // 15 kx * 1024
#define SQ1_SMEM (A_BYTES + B_BYTES)     // 222720

// ---- f32x2 helpers (head / sq2 FFMA kernels) ------------------------------
__device__ __forceinline__ void fma2(ull& d, ull a, ull b) {
    asm("fma.rn.f32x2 %0, %1, %2, %0;" : "+l"(d) : "l"(a), "l"(b));
}
__device__ __forceinline__ ull pack2(float lo, float hi) {
    ull r; asm("mov.b64 %0, {%1, %2};" : "=l"(r) : "f"(lo), "f"(hi)); return r;
}
__device__ __forceinline__ void unpack2(ull v, float& lo, float& hi) {
    asm("mov.b64 {%0, %1}, %2;" : "=f"(lo), "=f"(hi) : "l"(v));
}

// ---- HMMA helpers ---------------------------------------------------------
__device__ __forceinline__ uint32_t smem_u32(const void* p) {
    uint32_t a;
    asm("{ .reg .u64 t; cvta.to.shared.u64 t, %1; cvt.u32.u64 %0, t; }" : "=r"(a) : "l"(p));
    return a;
}
__device__ __forceinline__ void ldsm4(uint32_t& r0, uint32_t& r1, uint32_t& r2,
                                      uint32_t& r3, uint32_t a) {
    asm volatile("ldmatrix.sync.aligned.m8n8.x4.shared.b16 {%0,%1,%2,%3}, [%4];"
                 : "=r"(r0), "=r"(r1), "=r"(r2), "=r"(r3) : "r"(a));
}
__device__ __forceinline__ void mma_bf16(float* d, uint32_t a0, uint32_t a1,
                                         uint32_t a2, uint32_t a3,
                                         uint32_t b0, uint32_t b1) {
    asm volatile(
        "mma.sync.aligned.m16n8k16.row.col.f32.bf16.bf16.f32 "
        "{%0,%1,%2,%3}, {%4,%5,%6,%7}, {%8,%9}, {%0,%1,%2,%3};"
        : "+f"(d[0]), "+f"(d[1]), "+f"(d[2]), "+f"(d[3])
        : "r"(a0), "r"(a1), "r"(a2), "r"(a3), "r"(b0), "r"(b1));
}

// ---------------------------------------------------------------------------
// K1: leaky integration over T per TC slice + mean over TC.
// ---------------------------------------------------------------------------
__global__ void integrate_kernel(const float* __restrict__ x,
                                 const float* __restrict__ mtc_p,
                                 float* __restrict__ z) {
    int idx = blockIdx.x * blockDim.x + threadIdx.x;
    if (idx >= 4 * 2 * HW) return;
    int p  = idx & (HW - 1);
    int bc = idx >> 14;
    int c  = bc & 1;
    int b  = bc >> 1;

    float mtc = *mtc_p;
    float al[5], om[5];
#pragma unroll
    for (int tc = 0; tc < 5; ++tc) {
        float tau = mtc * exp2f(0.5f * (float)(tc - 2));
        al[tc] = expf(-1.0f / tau);
        om[tc] = 1.0f - al[tc];
    }
    float s[5] = {0.f, 0.f, 0.f, 0.f, 0.f};
    for (int t = 0; t < 16; ++t) {
        float acc = 0.f;
#pragma unroll
        for (int tc = 0; tc < 5; ++tc) {
            float v = x[(size_t)((t * 4 + b) * 10 + tc * 2 + c) * HW + p];
            s[tc] = al[tc] * s[tc] + om[tc] * v;
            acc += s[tc];
        }
        z[(size_t)((t * 4 + b) * 2 + c) * HW + p] = acc * 0.2f;
    }
}

// ---------------------------------------------------------------------------
// K2: head conv 2->16 (FFMA f32x2 path)
// ---------------------------------------------------------------------------
template <int CIN>
__global__ __launch_bounds__(256, 2)
void conv15_to16(const float* __restrict__ in, const float* __restrict__ w,
                 float* __restrict__ out) {
    __shared__ __align__(16) float tile[46 * 48];
    __shared__ __align__(16) float wsm[225 * 16];

    int img = blockIdx.y;
    int bx0 = (blockIdx.x & 3)  * 32;
    int by0 = (blockIdx.x >> 2) * 32;
    int tid = threadIdx.x;
    int tx  = tid & 31;
    int ty  = tid >> 5;

    ull acc[4][8];
#pragma unroll
    for (int r = 0; r < 4; ++r)
#pragma unroll
        for (int j = 0; j < 8; ++j) acc[r][j] = 0ull;

    for (int cin = 0; cin < CIN; ++cin) {
        __syncthreads();
        const float* src = in + ((size_t)img * CIN + cin) * HW;
        for (int i = tid; i < 46 * 46; i += 256) {
            int r  = i / 46, cc = i % 46;
            int gy = by0 + r - 7, gx = bx0 + cc - 7;
            float v = 0.f;
            if (gy >= 0 && gy < 128 && gx >= 0 && gx < 128) v = src[gy * 128 + gx];
            tile[r * 48 + cc] = v;
        }
        for (int i = tid; i < 225 * 16; i += 256) {
            int k = i >> 4, co = i & 15;
            wsm[i] = w[((size_t)co * CIN + cin) * 225 + k];
        }
        __syncthreads();

#pragma unroll 1
        for (int ky = 0; ky < 15; ++ky) {
            const float* trow = &tile[(ty + ky) * 48 + tx];
#pragma unroll
            for (int kx = 0; kx < 15; ++kx) {
                ull p0 = pack2(trow[kx],           trow[kx]);
                ull p1 = pack2(trow[kx +  8 * 48], trow[kx +  8 * 48]);
                ull p2 = pack2(trow[kx + 16 * 48], trow[kx + 16 * 48]);
                ull p3 = pack2(trow[kx + 24 * 48], trow[kx + 24 * 48]);
                const ull* wq = (const ull*)&wsm[(ky * 15 + kx) * 16];
#pragma unroll
                for (int j = 0; j < 8; ++j) {
                    ull wv = wq[j];
                    fma2(acc[0][j], p0, wv);
                    fma2(acc[1][j], p1, wv);
                    fma2(acc[2][j], p2, wv);
                    fma2(acc[3][j], p3, wv);
                }
            }
        }
    }

#pragma unroll
    for (int r = 0; r < 4; ++r) {
        int oy = by0 + ty + 8 * r;
#pragma unroll
        for (int j = 0; j < 8; ++j) {
            float lo, hi;
            unpack2(acc[r][j], lo, hi);
            out[((size_t)img * 16 + 2 * j)     * HW + oy * 128 + bx0 + tx] = lo;
            out[((size_t)img * 16 + 2 * j + 1) * HW + oy * 128 + bx0 + tx] = hi;
        }
    }
}

// ---------------------------------------------------------------------------
// K3a: prepass — each (img,y) row becomes 144 pixel records of 80B:
// [16 bf16 hi | 16 bf16 lo | 16B pad(0)]. Staged in smem for coalesced store.
// ---------------------------------------------------------------------------
__global__ __launch_bounds__(160, 4)
void split_rows(const float* __restrict__ in, uint8_t* __restrict__ xs) {
    __shared__ __align__(16) uint8_t rowbuf[144 * 80];
    int y = blockIdx.x, img = blockIdx.y;
    int p = threadIdx.x;

    if (p < 144) {
        int x = p - 7;
        bool valid = (x >= 0 && x < 128);
        __align__(16) __nv_bfloat16 hi[16], lo[16];
#pragma unroll
        for (int c = 0; c < 16; ++c) {
            float a = valid ? in[((size_t)(img * 16 + c) * 128 + y) * 128 + x] : 0.f;
            __nv_bfloat16 h = __float2bfloat16(a);
            hi[c] = h;
            lo[c] = __float2bfloat16(a - __bfloat162float(h));
        }
        uint8_t* rb = rowbuf + p * 80;
        *(uint4*)(rb +  0) = *(const uint4*)&hi[0];
        *(uint4*)(rb + 16) = *(const uint4*)&hi[8];
        *(uint4*)(rb + 32) = *(const uint4*)&lo[0];
        *(uint4*)(rb + 48) = *(const uint4*)&lo[8];
        *(uint4*)(rb + 64) = make_uint4(0, 0, 0, 0);
    }
    __syncthreads();
    uint8_t* dst = xs + (size_t)(img * 128 + y) * ROWB;
    for (int u = threadIdx.x; u < 720; u += 160)
        *(uint4*)(dst + u * 16) = *(const uint4*)(rowbuf + u * 16);
}

// ---------------------------------------------------------------------------
// K3b: prepass — split sq1 weights into per-(ky,kx) 1KB blocks:
// [co 16][cin 16] bf16 hi at +0, lo at +512. (ky*15+kx) blocks contiguous.
// ---------------------------------------------------------------------------
__global__ void split_weights(const float* __restrict__ w, uint8_t* __restrict__ ws) {
    int kxy = blockIdx.x;            // 0..224
    int t   = threadIdx.x;           // 0..255
    int co  = t >> 4, cin = t & 15;
    int ky  = kxy / 15, kx = kxy % 15;
    float wv = w[((size_t)(co * 16 + cin) * 15 + ky) * 15 + kx];
    __nv_bfloat16 h = __float2bfloat16(wv);
    __nv_bfloat16 l = __float2bfloat16(wv - __bfloat162float(h));
    uint8_t* dst = ws + (size_t)kxy * 1024 + co * 32 + cin * 2;
    *(__nv_bfloat16*)dst         = h;
    *(__nv_bfloat16*)(dst + 512) = l;
}

// ---------------------------------------------------------------------------
// K4: sq1 conv 16->16 via warp-level HMMA (mma.sync bf16, 3-term split).
// CTA = (image, 4 output rows); 16 warps: warp = (row, x-quarter), 2 M-tiles.
// 4 warps per SMSP for latency hiding. Epilogue staged via smem (coalesced).
// ---------------------------------------------------------------------------
__global__ __launch_bounds__(512, 1)
void conv_sq1_hmma(const uint8_t* __restrict__ xs, const uint8_t* __restrict__ ws,
                   float* __restrict__ out) {
    extern __shared__ __align__(16) uint8_t sm[];
    uint8_t* Asm = sm;
    uint8_t* Bsm = sm + A_BYTES;

    int tid  = threadIdx.x;
    int lane = tid & 31;
    int w    = tid >> 5;             // warp 0..15
    int r    = w >> 2;               // output row 0..3
    int qd   = w & 3;                // x quarter 0..3
    int grp  = blockIdx.x;           // 0..31
    int img  = blockIdx.y;           // 0..63
    int y0   = grp * 4;

    // ---- A ring: 18 input rows (y0-7 .. y0+10), zero-padded at edges ----
    const uint8_t* srcbase = xs + (size_t)img * 128 * ROWB;
    for (int u = tid; u < 18 * 720; u += 512) {
        int slot = u / 720, q = u % 720;
        int yin  = y0 - 7 + slot;
        uint4 v = make_uint4(0, 0, 0, 0);
        if (yin >= 0 && yin < 128)
            v = *(const uint4*)(srcbase + (size_t)yin * ROWB + q * 16);
        *(uint4*)(Asm + slot * ROWB + q * 16) = v;
    }

    uint32_t asm_base = smem_u32(Asm);
    uint32_t bsm_base = smem_u32(Bsm);
    int part = lane >> 3, rr = lane & 7;
    uint32_t a_off = (uint32_t)((((part & 1) << 3) + rr) * 80 + ((part >> 1) << 4));
    uint32_t b_off = (uint32_t)((((part >> 1) << 3) + rr) * 32 + ((part & 1) << 4));

    float acc[2][2][4];
#pragma unroll
    for (int t = 0; t < 2; ++t)
#pragma unroll
        for (int h = 0; h < 2; ++h)
#pragma unroll
            for (int i = 0; i < 4; ++i) acc[t][h][i] = 0.f;

#pragma unroll 1
    for (int ky = 0; ky < 15; ++ky) {
        __syncthreads();                       // A ready / previous B consumed
        const uint8_t* bw = ws + (size_t)ky * B_BYTES;
        for (int u = tid; u < 960; u += 512)
            *(uint4*)(Bsm + u * 16) = *(const uint4*)(bw + u * 16);
        __syncthreads();

        uint32_t arow = asm_base + (uint32_t)((r + ky) * ROWB) + a_off;

#pragma unroll 1
        for (int kx = 0; kx < 15; ++kx) {
            uint32_t baddr = bsm_base + kx * 1024 + b_off;
            uint32_t bh0, bh1, bh2, bh3, bl0, bl1, bl2, bl3;
            ldsm4(bh0, bh1, bh2, bh3, baddr);
            ldsm4(bl0, bl1, bl2, bl3, baddr + 512);
            uint32_t abase = arow + kx * 80;
#pragma unroll
            for (int t = 0; t < 2; ++t) {
                int tt = qd * 2 + t;           // M-tile 0..7
                uint32_t aaddr = abase + tt * 1280;
                uint32_t ah0, ah1, ah2, ah3, al0, al1, al2, al3;
                ldsm4(ah0, ah1, ah2, ah3, aaddr);
                ldsm4(al0, al1, al2, al3, aaddr + 32);
                mma_bf16(acc[t][0], ah0, ah1, ah2, ah3, bh0, bh1);
                mma_bf16(acc[t][1], ah0, ah1, ah2, ah3, bh2, bh3);
                mma_bf16(acc[t][0], ah0, ah1, ah2, ah3, bl0, bl1);
                mma_bf16(acc[t][1], ah0, ah1, ah2, ah3, bl2, bl3);
                mma_bf16(acc[t][0], al0, al1, al2, al3, bh0, bh1);
                mma_bf16(acc[t][1], al0, al1, al2, al3, bh2, bh3);
            }
        }
    }

    // ---- epilogue: stage D fragments in smem (A ring reusable), then
    //      coalesced float4 stores to g_h1[img][co][y][x] ----
    __syncthreads();
    float* stage = (float*)Asm;                // [row 4][co 16][x 128] = 32KB
    {
        int q  = lane >> 2;
        int cb = (lane & 3) * 2;
#pragma unroll
        for (int t = 0; t < 2; ++t) {
            int tt = qd * 2 + t;
            int x  = tt * 16 + q;
#pragma unroll
            for (int h = 0; h < 2; ++h) {
                int co = h * 8 + cb;
                stage[(r * 16 + co)     * 128 + x    ] = acc[t][h][0];
                stage[(r * 16 + co + 1) * 128 + x    ] = acc[t][h][1];
                stage[(r * 16 + co)     * 128 + x + 8] = acc[t][h][2];
                stage[(r * 16 + co + 1) * 128 + x + 8] = acc[t][h][3];
            }
        }
    }
    __syncthreads();
    for (int i = tid; i < 2048; i += 512) {    // 2048 float4 = 4 rows x 16co x 128x
        int rw  = i >> 9;                      // 0..3
        int rem = i & 511;
        int co  = rem >> 5;
        int x4  = rem & 31;
        float4 v = *(const float4*)&stage[(rw * 16 + co) * 128 + x4 * 4];
        *(float4*)&out[((size_t)(img * 16 + co) * 128 + (y0 + rw)) * 128 + x4 * 4] = v;
    }
}

// ---------------------------------------------------------------------------
// K5: 15x15 conv 16 -> 1 fused with 2x2 max pool (f32x2 path)
// ---------------------------------------------------------------------------
__global__ __launch_bounds__(256, 2)
void conv_sq2_pool(const float* __restrict__ in, const float* __restrict__ w,
                   float* __restrict__ out) {
    __shared__ __align__(16) float tile[46 * 48];
    __shared__ __align__(16) ull  wsm2[225];
    __shared__ float ctile[32 * 32];

    int img = blockIdx.y;
    int bx0 = (blockIdx.x & 3)  * 32;
    int by0 = (blockIdx.x >> 2) * 32;
    int tid = threadIdx.x;
    int tx  = tid & 7;
    int ty  = tid >> 3;

    ull accA = 0ull, accB = 0ull;

    for (int cin = 0; cin < 16; ++cin) {
        __syncthreads();
        const float* src = in + ((size_t)img * 16 + cin) * HW;
        for (int i = tid; i < 46 * 46; i += 256) {
            int r  = i / 46, cc = i % 46;
            int gy = by0 + r - 7, gx = bx0 + cc - 7;
            float v = 0.f;
            if (gy >= 0 && gy < 128 && gx >= 0 && gx < 128) v = src[gy * 128 + gx];
            tile[r * 48 + cc] = v;
        }
        if (tid < 225) {
            float wv = w[cin * 225 + tid];
            wsm2[tid] = pack2(wv, wv);
        }
        __syncthreads();

#pragma unroll 1
        for (int ky = 0; ky < 15; ++ky) {
            const float4* trow = (const float4*)&tile[(ty + ky) * 48 + 4 * tx];
            float4 v0 = trow[0], v1 = trow[1], v2 = trow[2], v3 = trow[3], v4 = trow[4];
            float rr[20] = {v0.x, v0.y, v0.z, v0.w, v1.x, v1.y, v1.z, v1.w,
                            v2.x, v2.y, v2.z, v2.w, v3.x, v3.y, v3.z, v3.w,
                            v4.x, v4.y, v4.z, v4.w};
            ull pr[17];
#pragma unroll
            for (int k = 0; k < 17; ++k) pr[k] = pack2(rr[k], rr[k + 1]);
            const ull* wrow = &wsm2[ky * 15];
#pragma unroll
            for (int kx = 0; kx < 15; ++kx) {
                ull wv = wrow[kx];
                fma2(accA, pr[kx],     wv);
                fma2(accB, pr[kx + 2], wv);
            }
        }
    }

    __syncthreads();
    {
        float o0, o1, o2, o3;
        unpack2(accA, o0, o1);
        unpack2(accB, o2, o3);
        ctile[ty * 32 + 4 * tx + 0] = o0;
        ctile[ty * 32 + 4 * tx + 1] = o1;
        ctile[ty * 32 + 4 * tx + 2] = o2;
        ctile[ty * 32 + 4 * tx + 3] = o3;
    }
    __syncthreads();

    int px = tid & 15, py = tid >> 4;
    float m = fmaxf(fmaxf(ctile[(2 * py) * 32 + 2 * px],     ctile[(2 * py) * 32 + 2 * px + 1]),
                    fmaxf(ctile[(2 * py + 1) * 32 + 2 * px], ctile[(2 * py + 1) * 32 + 2 * px + 1]));
    out[(size_t)img * 4096 + (by0 / 2 + py) * 64 + (bx0 / 2 + px)] = m;
}

// ---------------------------------------------------------------------------
// K6: softmax over 64x64 heatmap + soft-argmax. One block per image.
// ---------------------------------------------------------------------------
__global__ void softargmax_kernel(const float* __restrict__ heat,
                                  float* __restrict__ coords) {
    __shared__ float red[256];
    int img = blockIdx.x, tid = threadIdx.x;
    const float* h = heat + (size_t)img * 4096;

    float v[16];
    float m = -1e30f;
#pragma unroll
    for (int i = 0; i < 16; ++i) { v[i] = h[tid + 256 * i]; m = fmaxf(m, v[i]); }

    red[tid] = m; __syncthreads();
    for (int s = 128; s > 0; s >>= 1) {
        if (tid < s) red[tid] = fmaxf(red[tid], red[tid + s]);
        __syncthreads();
    }
    m = red[0]; __syncthreads();

    float se = 0.f, sx = 0.f, sy = 0.f;
#pragma unroll
    for (int i = 0; i < 16; ++i) {
        int k = tid + 256 * i;
        float e = expf(v[i] - m);
        se += e;
        sx += e * (float)(k & 63);
        sy += e * (float)(k >> 6);
    }

    red[tid] = se; __syncthreads();
    for (int s = 128; s > 0; s >>= 1) { if (tid < s) red[tid] += red[tid + s]; __syncthreads(); }
    float tot = red[0]; __syncthreads();

    red[tid] = sx; __syncthreads();
    for (int s = 128; s > 0; s >>= 1) { if (tid < s) red[tid] += red[tid + s]; __syncthreads(); }
    float totx = red[0]; __syncthreads();

    red[tid] = sy; __syncthreads();
    for (int s = 128; s > 0; s >>= 1) { if (tid < s) red[tid] += red[tid + s]; __syncthreads(); }
    float toty = red[0];

    if (tid == 0) {
        coords[img * 2 + 0] = totx / (63.0f * tot);
        coords[img * 2 + 1] = toty / (63.0f * tot);
    }
}

// ---------------------------------------------------------------------------
extern "C" void kernel_launch(void* const* d_in, const int* in_sizes, int n_in,
                              void* d_out, int out_size) {
    const float* x      = (const float*)d_in[0];
    const float* head_w = (const float*)d_in[1];
    const float* sq1_w  = (const float*)d_in[2];
    const float* sq2_w  = (const float*)d_in[3];
    const float* mtc    = (const float*)d_in[4];
    float* out = (float*)d_out;

    float *zp, *xmp, *h1p;
    uint8_t *xsp, *wsp;
    cudaGetSymbolAddress((void**)&zp,  g_z);
    cudaGetSymbolAddress((void**)&xmp, g_xm);
    cudaGetSymbolAddress((void**)&h1p, g_h1);
    cudaGetSymbolAddress((void**)&xsp, g_xs);
    cudaGetSymbolAddress((void**)&wsp, g_ws);

    cudaFuncSetAttribute(conv_sq1_hmma,
                         cudaFuncAttributeMaxDynamicSharedMemorySize, SQ1_SMEM);

    integrate_kernel<<<512, 256>>>(x, mtc, zp);
    split_weights<<<225, 256>>>(sq1_w, wsp);
    conv15_to16<2><<<dim3(16, NIMG), 256>>>(zp, head_w, xmp);
    split_rows<<<dim3(128, NIMG), 160>>>(xmp, xsp);
    conv_sq1_hmma<<<dim3(32, NIMG), 512, SQ1_SMEM>>>(xsp, wsp, h1p);
    conv_sq2_pool<<<dim3(16, NIMG), 256>>>(h1p, sq2_w, out);

    if (out_size >= NIMG * 4096 + NIMG * 2) {
        softargmax_kernel<<<NIMG, 256>>>(out, out + (size_t)NIMG * 4096);
    }
}

// round 7
// speedup vs baseline: 2.2237x; 1.1482x over previous
#include <cuda_runtime.h>
#include <cuda_bf16.h>
#include <cuda_fp16.h>
#include <math.h>
#include <stdint.h>

#define NIMG 64          // T*B = 16*4
#define HW   16384       // 128*128
typedef unsigned long long ull;

// Scratch (allocation-free rule: __device__ globals)
__device__ float   g_z [NIMG *  2 * HW];                 //  8 MB integrated input
__device__ float   g_xm[NIMG * 16 * HW];                 // 64 MB head conv output
__device__ float   g_h1[NIMG * 16 * HW];                 // 64 MB sq1 conv output
__device__ uint8_t g_xs[(size_t)NIMG * 128 * 144 * 48];  // 56.6 MB fp16 pixel rows
__device__ uint8_t g_ws[225 * 1024];                     // split fp16 weights (x1024)

#define ROWB 6912                        // 144 px * 48 B
#define A_BYTES (18 * ROWB)              // 124416
#define B_SLICE 15360                    // 15 kx * 1024
#define SQ1_SMEM (A_BYTES + 2 * B_SLICE) // 155136 (B double-buffered)

// ---- f32x2 helpers --------------------------------------------------------
__device__ __forceinline__ void fma2(ull& d, ull a, ull b) {
    asm("fma.rn.f32x2 %0, %1, %2, %0;" : "+l"(d) : "l"(a), "l"(b));
}
__device__ __forceinline__ ull pack2(float lo, float hi) {
    ull r; asm("mov.b64 %0, {%1, %2};" : "=l"(r) : "f"(lo), "f"(hi)); return r;
}
__device__ __forceinline__ void unpack2(ull v, float& lo, float& hi) {
    asm("mov.b64 {%0, %1}, %2;" : "=f"(lo), "=f"(hi) : "l"(v));
}

// ---- HMMA helpers ---------------------------------------------------------
__device__ __forceinline__ uint32_t smem_u32(const void* p) {
    uint32_t a;
    asm("{ .reg .u64 t; cvta.to.shared.u64 t, %1; cvt.u32.u64 %0, t; }" : "=r"(a) : "l"(p));
    return a;
}
__device__ __forceinline__ void ldsm4(uint32_t& r0, uint32_t& r1, uint32_t& r2,
                                      uint32_t& r3, uint32_t a) {
    asm volatile("ldmatrix.sync.aligned.m8n8.x4.shared.b16 {%0,%1,%2,%3}, [%4];"
                 : "=r"(r0), "=r"(r1), "=r"(r2), "=r"(r3) : "r"(a));
}
__device__ __forceinline__ void mma_f16(float* d, uint32_t a0, uint32_t a1,
                                        uint32_t a2, uint32_t a3,
                                        uint32_t b0, uint32_t b1) {
    asm volatile(
        "mma.sync.aligned.m16n8k16.row.col.f32.f16.f16.f32 "
        "{%0,%1,%2,%3}, {%4,%5,%6,%7}, {%8,%9}, {%0,%1,%2,%3};"
        : "+f"(d[0]), "+f"(d[1]), "+f"(d[2]), "+f"(d[3])
        : "r"(a0), "r"(a1), "r"(a2), "r"(a3), "r"(b0), "r"(b1));
}

// ---------------------------------------------------------------------------
// K1: leaky integration over T per TC slice + mean over TC.
// ---------------------------------------------------------------------------
__global__ void integrate_kernel(const float* __restrict__ x,
                                 const float* __restrict__ mtc_p,
                                 float* __restrict__ z) {
    int idx = blockIdx.x * blockDim.x + threadIdx.x;
    if (idx >= 4 * 2 * HW) return;
    int p  = idx & (HW - 1);
    int bc = idx >> 14;
    int c  = bc & 1;
    int b  = bc >> 1;

    float mtc = *mtc_p;
    float al[5], om[5];
#pragma unroll
    for (int tc = 0; tc < 5; ++tc) {
        float tau = mtc * exp2f(0.5f * (float)(tc - 2));
        al[tc] = expf(-1.0f / tau);
        om[tc] = 1.0f - al[tc];
    }
    float s[5] = {0.f, 0.f, 0.f, 0.f, 0.f};
    for (int t = 0; t < 16; ++t) {
        float acc = 0.f;
#pragma unroll
        for (int tc = 0; tc < 5; ++tc) {
            float v = x[(size_t)((t * 4 + b) * 10 + tc * 2 + c) * HW + p];
            s[tc] = al[tc] * s[tc] + om[tc] * v;
            acc += s[tc];
        }
        z[(size_t)((t * 4 + b) * 2 + c) * HW + p] = acc * 0.2f;
    }
}

// ---------------------------------------------------------------------------
// K2: head conv 2->16 (FFMA f32x2 path)
// ---------------------------------------------------------------------------
template <int CIN>
__global__ __launch_bounds__(256, 2)
void conv15_to16(const float* __restrict__ in, const float* __restrict__ w,
                 float* __restrict__ out) {
    __shared__ __align__(16) float tile[46 * 48];
    __shared__ __align__(16) float wsm[225 * 16];

    int img = blockIdx.y;
    int bx0 = (blockIdx.x & 3)  * 32;
    int by0 = (blockIdx.x >> 2) * 32;
    int tid = threadIdx.x;
    int tx  = tid & 31;
    int ty  = tid >> 5;

    ull acc[4][8];
#pragma unroll
    for (int r = 0; r < 4; ++r)
#pragma unroll
        for (int j = 0; j < 8; ++j) acc[r][j] = 0ull;

    for (int cin = 0; cin < CIN; ++cin) {
        __syncthreads();
        const float* src = in + ((size_t)img * CIN + cin) * HW;
        for (int i = tid; i < 46 * 46; i += 256) {
            int r  = i / 46, cc = i % 46;
            int gy = by0 + r - 7, gx = bx0 + cc - 7;
            float v = 0.f;
            if (gy >= 0 && gy < 128 && gx >= 0 && gx < 128) v = src[gy * 128 + gx];
            tile[r * 48 + cc] = v;
        }
        for (int i = tid; i < 225 * 16; i += 256) {
            int k = i >> 4, co = i & 15;
            wsm[i] = w[((size_t)co * CIN + cin) * 225 + k];
        }
        __syncthreads();

#pragma unroll 1
        for (int ky = 0; ky < 15; ++ky) {
            const float* trow = &tile[(ty + ky) * 48 + tx];
#pragma unroll
            for (int kx = 0; kx < 15; ++kx) {
                ull p0 = pack2(trow[kx],           trow[kx]);
                ull p1 = pack2(trow[kx +  8 * 48], trow[kx +  8 * 48]);
                ull p2 = pack2(trow[kx + 16 * 48], trow[kx + 16 * 48]);
                ull p3 = pack2(trow[kx + 24 * 48], trow[kx + 24 * 48]);
                const ull* wq = (const ull*)&wsm[(ky * 15 + kx) * 16];
#pragma unroll
                for (int j = 0; j < 8; ++j) {
                    ull wv = wq[j];
                    fma2(acc[0][j], p0, wv);
                    fma2(acc[1][j], p1, wv);
                    fma2(acc[2][j], p2, wv);
                    fma2(acc[3][j], p3, wv);
                }
            }
        }
    }

#pragma unroll
    for (int r = 0; r < 4; ++r) {
        int oy = by0 + ty + 8 * r;
#pragma unroll
        for (int j = 0; j < 8; ++j) {
            float lo, hi;
            unpack2(acc[r][j], lo, hi);
            out[((size_t)img * 16 + 2 * j)     * HW + oy * 128 + bx0 + tx] = lo;
            out[((size_t)img * 16 + 2 * j + 1) * HW + oy * 128 + bx0 + tx] = hi;
        }
    }
}

// ---------------------------------------------------------------------------
// K3a: prepass — each (img,y) row becomes 144 pixel records of 48B:
// [16 fp16 (32B) | 16B pad(0)]. 3-unit stride => conflict-free ldmatrix.
// ---------------------------------------------------------------------------
__global__ __launch_bounds__(160, 4)
void split_rows(const float* __restrict__ in, uint8_t* __restrict__ xs) {
    __shared__ __align__(16) uint8_t rowbuf[144 * 48];
    int y = blockIdx.x, img = blockIdx.y;
    int p = threadIdx.x;

    if (p < 144) {
        int x = p - 7;
        bool valid = (x >= 0 && x < 128);
        __align__(16) __half h[16];
#pragma unroll
        for (int c = 0; c < 16; ++c) {
            float a = valid ? in[((size_t)(img * 16 + c) * 128 + y) * 128 + x] : 0.f;
            h[c] = __float2half_rn(a);
        }
        uint8_t* rb = rowbuf + p * 48;
        *(uint4*)(rb +  0) = *(const uint4*)&h[0];
        *(uint4*)(rb + 16) = *(const uint4*)&h[8];
        *(uint4*)(rb + 32) = make_uint4(0, 0, 0, 0);
    }
    __syncthreads();
    uint8_t* dst = xs + (size_t)(img * 128 + y) * ROWB;
    for (int u = threadIdx.x; u < 432; u += 160)
        *(uint4*)(dst + u * 16) = *(const uint4*)(rowbuf + u * 16);
}

// ---------------------------------------------------------------------------
// K3b: prepass — split sq1 weights (x1024 to dodge fp16 denormals) into
// per-(ky,kx) 1KB blocks: [co 16][cin 16] fp16 hi at +0, lo at +512.
// ---------------------------------------------------------------------------
__global__ void split_weights(const float* __restrict__ w, uint8_t* __restrict__ ws) {
    int kxy = blockIdx.x;            // 0..224
    int t   = threadIdx.x;           // 0..255
    int co  = t >> 4, cin = t & 15;
    int ky  = kxy / 15, kx = kxy % 15;
    float wv = w[((size_t)(co * 16 + cin) * 15 + ky) * 15 + kx] * 1024.0f;
    __half h = __float2half_rn(wv);
    __half l = __float2half_rn(wv - __half2float(h));
    uint8_t* dst = ws + (size_t)kxy * 1024 + co * 32 + cin * 2;
    *(__half*)dst         = h;
    *(__half*)(dst + 512) = l;
}

// ---------------------------------------------------------------------------
// K4: sq1 conv 16->16 via fp16 HMMA, 2-term B-split (A single fp16).
// CTA = (image, 4 output rows); 16 warps = (row, x-quarter) x 2 M-tiles.
// B double-buffered: one barrier per ky. Epilogue scales by 2^-10.
// ---------------------------------------------------------------------------
__global__ __launch_bounds__(512, 1)
void conv_sq1_hmma(const uint8_t* __restrict__ xs, const uint8_t* __restrict__ ws,
                   float* __restrict__ out) {
    extern __shared__ __align__(16) uint8_t sm[];
    uint8_t* Asm = sm;
    uint8_t* Bsm = sm + A_BYTES;     // 2 x B_SLICE

    int tid  = threadIdx.x;
    int lane = tid & 31;
    int w    = tid >> 5;             // warp 0..15
    int r    = w >> 2;               // output row 0..3
    int qd   = w & 3;                // x quarter 0..3
    int grp  = blockIdx.x;           // 0..31
    int img  = blockIdx.y;           // 0..63
    int y0   = grp * 4;

    // ---- A ring: 18 input rows (y0-7 .. y0+10), zero-padded at edges ----
    const uint8_t* srcbase = xs + (size_t)img * 128 * ROWB;
    for (int u = tid; u < 18 * 432; u += 512) {
        int slot = u / 432, q = u % 432;
        int yin  = y0 - 7 + slot;
        uint4 v = make_uint4(0, 0, 0, 0);
        if (yin >= 0 && yin < 128)
            v = *(const uint4*)(srcbase + (size_t)yin * ROWB + q * 16);
        *(uint4*)(Asm + slot * ROWB + q * 16) = v;
    }
    // ---- preload B slice ky=0 into buffer 0 ----
    for (int u = tid; u < 960; u += 512)
        *(uint4*)(Bsm + u * 16) = *(const uint4*)(ws + u * 16);

    uint32_t asm_base = smem_u32(Asm);
    uint32_t bsm_base = smem_u32(Bsm);
    int part = lane >> 3, rr = lane & 7;
    uint32_t a_off = (uint32_t)((((part & 1) << 3) + rr) * 48 + ((part >> 1) << 4));
    uint32_t b_off = (uint32_t)((((part >> 1) << 3) + rr) * 32 + ((part & 1) << 4));

    float acc[2][2][4];
#pragma unroll
    for (int t = 0; t < 2; ++t)
#pragma unroll
        for (int h = 0; h < 2; ++h)
#pragma unroll
            for (int i = 0; i < 4; ++i) acc[t][h][i] = 0.f;

    __syncthreads();

#pragma unroll 1
    for (int ky = 0; ky < 15; ++ky) {
        if (ky) __syncthreads();
        if (ky < 14) {                           // prefetch next B slice
            const uint8_t* bw = ws + (size_t)(ky + 1) * B_SLICE;
            uint8_t* bdst = Bsm + ((ky + 1) & 1) * B_SLICE;
            for (int u = tid; u < 960; u += 512)
                *(uint4*)(bdst + u * 16) = *(const uint4*)(bw + u * 16);
        }
        uint32_t bcur = bsm_base + (uint32_t)((ky & 1) * B_SLICE);
        uint32_t arow = asm_base + (uint32_t)((r + ky) * ROWB) + a_off;

#pragma unroll 1
        for (int kx = 0; kx < 15; ++kx) {
            uint32_t baddr = bcur + kx * 1024 + b_off;
            uint32_t bh0, bh1, bh2, bh3, bl0, bl1, bl2, bl3;
            ldsm4(bh0, bh1, bh2, bh3, baddr);
            ldsm4(bl0, bl1, bl2, bl3, baddr + 512);
            uint32_t abase = arow + kx * 48;
#pragma unroll
            for (int t = 0; t < 2; ++t) {
                int tt = qd * 2 + t;             // M-tile 0..7
                uint32_t aaddr = abase + tt * 768;
                uint32_t a0, a1, a2, a3;
                ldsm4(a0, a1, a2, a3, aaddr);
                mma_f16(acc[t][0], a0, a1, a2, a3, bh0, bh1);
                mma_f16(acc[t][1], a0, a1, a2, a3, bh2, bh3);
                mma_f16(acc[t][0], a0, a1, a2, a3, bl0, bl1);
                mma_f16(acc[t][1], a0, a1, a2, a3, bl2, bl3);
            }
        }
    }

    // ---- epilogue: scale back 2^-10, stage in smem, coalesced stores ----
    __syncthreads();
    float* stage = (float*)Asm;                  // 32KB needed, fits in A ring
    {
        const float sc = 1.0f / 1024.0f;
        int q  = lane >> 2;
        int cb = (lane & 3) * 2;
#pragma unroll
        for (int t = 0; t < 2; ++t) {
            int tt = qd * 2 + t;
            int x  = tt * 16 + q;
#pragma unroll
            for (int h = 0; h < 2; ++h) {
                int co = h * 8 + cb;
                stage[(r * 16 + co)     * 128 + x    ] = acc[t][h][0] * sc;
                stage[(r * 16 + co + 1) * 128 + x    ] = acc[t][h][1] * sc;
                stage[(r * 16 + co)     * 128 + x + 8] = acc[t][h][2] * sc;
                stage[(r * 16 + co + 1) * 128 + x + 8] = acc[t][h][3] * sc;
            }
        }
    }
    __syncthreads();
    for (int i = tid; i < 2048; i += 512) {
        int rw  = i >> 9;
        int rem = i & 511;
        int co  = rem >> 5;
        int x4  = rem & 31;
        float4 v = *(const float4*)&stage[(rw * 16 + co) * 128 + x4 * 4];
        *(float4*)&out[((size_t)(img * 16 + co) * 128 + (y0 + rw)) * 128 + x4 * 4] = v;
    }
}

// ---------------------------------------------------------------------------
// K5: 15x15 conv 16 -> 1 fused with 2x2 max pool. Row-reuse: each thread
// computes 4x * 2y outputs; each loaded row window feeds both y-rows.
// ---------------------------------------------------------------------------
__global__ __launch_bounds__(256, 2)
void conv_sq2_pool(const float* __restrict__ in, const float* __restrict__ w,
                   float* __restrict__ out) {
    __shared__ __align__(16) float tile[78 * 48];    // rows 0..77, cols 0..45 (pad 48)
    __shared__ __align__(16) ull  wsm2[225];
    __shared__ float ctile[64 * 32];                 // [y][x]

    int img = blockIdx.y;
    int bx0 = (blockIdx.x & 3)  * 32;                // 4 x-blocks
    int by0 = (blockIdx.x >> 2) * 64;                // 2 y-blocks
    int tid = threadIdx.x;
    int tx  = tid & 7;                               // x-group (4 px)
    int tyg = tid >> 3;                              // 0..31 (2 rows each)

    ull acc[2][2];                                   // [y r][x pair]
    acc[0][0] = acc[0][1] = acc[1][0] = acc[1][1] = 0ull;

    for (int cin = 0; cin < 16; ++cin) {
        __syncthreads();
        const float* src = in + ((size_t)img * 16 + cin) * HW;
        for (int i = tid; i < 78 * 46; i += 256) {
            int rrow = i / 46, cc = i % 46;
            int gy = by0 + rrow - 7, gx = bx0 + cc - 7;
            float v = 0.f;
            if (gy >= 0 && gy < 128 && gx >= 0 && gx < 128) v = src[gy * 128 + gx];
            tile[rrow * 48 + cc] = v;
        }
        if (tid < 225) {
            float wv = w[cin * 225 + tid];
            wsm2[tid] = pack2(wv, wv);
        }
        __syncthreads();

#pragma unroll 1
        for (int s = 0; s < 16; ++s) {
            int trow = tyg * 2 + s;
            const float4* tp = (const float4*)&tile[trow * 48 + 4 * tx];
            float4 v0 = tp[0], v1 = tp[1], v2 = tp[2], v3 = tp[3], v4 = tp[4];
            float rv[20] = {v0.x, v0.y, v0.z, v0.w, v1.x, v1.y, v1.z, v1.w,
                            v2.x, v2.y, v2.z, v2.w, v3.x, v3.y, v3.z, v3.w,
                            v4.x, v4.y, v4.z, v4.w};
            ull pr[17];
#pragma unroll
            for (int k = 0; k < 17; ++k) pr[k] = pack2(rv[k], rv[k + 1]);
            if (s < 15) {
                const ull* wrow = &wsm2[s * 15];
#pragma unroll
                for (int kx = 0; kx < 15; ++kx) {
                    ull wv = wrow[kx];
                    fma2(acc[0][0], pr[kx],     wv);
                    fma2(acc[0][1], pr[kx + 2], wv);
                }
            }
            if (s >= 1) {
                const ull* wrow = &wsm2[(s - 1) * 15];
#pragma unroll
                for (int kx = 0; kx < 15; ++kx) {
                    ull wv = wrow[kx];
                    fma2(acc[1][0], pr[kx],     wv);
                    fma2(acc[1][1], pr[kx + 2], wv);
                }
            }
        }
    }

    __syncthreads();
#pragma unroll
    for (int r = 0; r < 2; ++r) {
        float o0, o1, o2, o3;
        unpack2(acc[r][0], o0, o1);
        unpack2(acc[r][1], o2, o3);
        float* cr = &ctile[(tyg * 2 + r) * 32 + 4 * tx];
        cr[0] = o0; cr[1] = o1; cr[2] = o2; cr[3] = o3;
    }
    __syncthreads();

    // 2x2 max pool: 16x32 pooled outputs per block, 2 per thread
    int px = tid & 15, py0 = tid >> 4;               // py0 0..15
#pragma unroll
    for (int hh = 0; hh < 2; ++hh) {
        int py = py0 + hh * 16;                      // 0..31
        float m = fmaxf(fmaxf(ctile[(2 * py) * 32 + 2 * px],     ctile[(2 * py) * 32 + 2 * px + 1]),
                        fmaxf(ctile[(2 * py + 1) * 32 + 2 * px], ctile[(2 * py + 1) * 32 + 2 * px + 1]));
        out[(size_t)img * 4096 + (by0 / 2 + py) * 64 + (bx0 / 2 + px)] = m;
    }
}

// ---------------------------------------------------------------------------
// K6: softmax over 64x64 heatmap + soft-argmax. One block per image.
// ---------------------------------------------------------------------------
__global__ void softargmax_kernel(const float* __restrict__ heat,
                                  float* __restrict__ coords) {
    __shared__ float red[256];
    int img = blockIdx.x, tid = threadIdx.x;
    const float* h = heat + (size_t)img * 4096;

    float v[16];
    float m = -1e30f;
#pragma unroll
    for (int i = 0; i < 16; ++i) { v[i] = h[tid + 256 * i]; m = fmaxf(m, v[i]); }

    red[tid] = m; __syncthreads();
    for (int s = 128; s > 0; s >>= 1) {
        if (tid < s) red[tid] = fmaxf(red[tid], red[tid + s]);
        __syncthreads();
    }
    m = red[0]; __syncthreads();

    float se = 0.f, sx = 0.f, sy = 0.f;
#pragma unroll
    for (int i = 0; i < 16; ++i) {
        int k = tid + 256 * i;
        float e = expf(v[i] - m);
        se += e;
        sx += e * (float)(k & 63);
        sy += e * (float)(k >> 6);
    }

    red[tid] = se; __syncthreads();
    for (int s = 128; s > 0; s >>= 1) { if (tid < s) red[tid] += red[tid + s]; __syncthreads(); }
    float tot = red[0]; __syncthreads();

    red[tid] = sx; __syncthreads();
    for (int s = 128; s > 0; s >>= 1) { if (tid < s) red[tid] += red[tid + s]; __syncthreads(); }
    float totx = red[0]; __syncthreads();

    red[tid] = sy; __syncthreads();
    for (int s = 128; s > 0; s >>= 1) { if (tid < s) red[tid] += red[tid + s]; __syncthreads(); }
    float toty = red[0];

    if (tid == 0) {
        coords[img * 2 + 0] = totx / (63.0f * tot);
        coords[img * 2 + 1] = toty / (63.0f * tot);
    }
}

// ---------------------------------------------------------------------------
extern "C" void kernel_launch(void* const* d_in, const int* in_sizes, int n_in,
                              void* d_out, int out_size) {
    const float* x      = (const float*)d_in[0];
    const float* head_w = (const float*)d_in[1];
    const float* sq1_w  = (const float*)d_in[2];
    const float* sq2_w  = (const float*)d_in[3];
    const float* mtc    = (const float*)d_in[4];
    float* out = (float*)d_out;

    float *zp, *xmp, *h1p;
    uint8_t *xsp, *wsp;
    cudaGetSymbolAddress((void**)&zp,  g_z);
    cudaGetSymbolAddress((void**)&xmp, g_xm);
    cudaGetSymbolAddress((void**)&h1p, g_h1);
    cudaGetSymbolAddress((void**)&xsp, g_xs);
    cudaGetSymbolAddress((void**)&wsp, g_ws);

    cudaFuncSetAttribute(conv_sq1_hmma,
                         cudaFuncAttributeMaxDynamicSharedMemorySize, SQ1_SMEM);

    integrate_kernel<<<512, 256>>>(x, mtc, zp);
    split_weights<<<225, 256>>>(sq1_w, wsp);
    conv15_to16<2><<<dim3(16, NIMG), 256>>>(zp, head_w, xmp);
    split_rows<<<dim3(128, NIMG), 160>>>(xmp, xsp);
    conv_sq1_hmma<<<dim3(32, NIMG), 512, SQ1_SMEM>>>(xsp, wsp, h1p);
    conv_sq2_pool<<<dim3(8, NIMG), 256>>>(h1p, sq2_w, out);

    if (out_size >= NIMG * 4096 + NIMG * 2) {
        softargmax_kernel<<<NIMG, 256>>>(out, out + (size_t)NIMG * 4096);
    }
}

// round 8
// speedup vs baseline: 2.8369x; 1.2757x over previous
#include <cuda_runtime.h>
#include <cuda_bf16.h>
#include <cuda_fp16.h>
#include <math.h>
#include <stdint.h>

#define NIMG 64          // T*B = 16*4
#define HW   16384       // 128*128
typedef unsigned long long ull;

// Scratch (allocation-free rule: __device__ globals)
__device__ float   g_z [NIMG *  2 * HW];                 //  8 MB integrated input
__device__ float   g_xm[NIMG * 16 * HW];                 // 64 MB head conv output
__device__ float   g_h1[NIMG * 16 * HW];                 // 64 MB sq1 conv output
__device__ uint8_t g_xs[(size_t)NIMG * 128 * 144 * 48];  // 56.6 MB fp16 pixel rows
__device__ uint8_t g_ws[225 * 512];                      // fp16 weights (x1024)

#define ROWB 6912                        // 144 px * 48 B
#define A_BYTES (18 * ROWB)              // 124416
#define B_SLICE 7680                     // 15 kx * 512
#define SQ1_SMEM (A_BYTES + 2 * B_SLICE) // 139776 (B double-buffered)

// ---- f32x2 helpers --------------------------------------------------------
__device__ __forceinline__ void fma2(ull& d, ull a, ull b) {
    asm("fma.rn.f32x2 %0, %1, %2, %0;" : "+l"(d) : "l"(a), "l"(b));
}
__device__ __forceinline__ ull pack2(float lo, float hi) {
    ull r; asm("mov.b64 %0, {%1, %2};" : "=l"(r) : "f"(lo), "f"(hi)); return r;
}
__device__ __forceinline__ void unpack2(ull v, float& lo, float& hi) {
    asm("mov.b64 {%0, %1}, %2;" : "=f"(lo), "=f"(hi) : "l"(v));
}

// ---- HMMA helpers ---------------------------------------------------------
__device__ __forceinline__ uint32_t smem_u32(const void* p) {
    uint32_t a;
    asm("{ .reg .u64 t; cvta.to.shared.u64 t, %1; cvt.u32.u64 %0, t; }" : "=r"(a) : "l"(p));
    return a;
}
__device__ __forceinline__ void ldsm4(uint32_t& r0, uint32_t& r1, uint32_t& r2,
                                      uint32_t& r3, uint32_t a) {
    asm volatile("ldmatrix.sync.aligned.m8n8.x4.shared.b16 {%0,%1,%2,%3}, [%4];"
                 : "=r"(r0), "=r"(r1), "=r"(r2), "=r"(r3) : "r"(a));
}
__device__ __forceinline__ void mma_f16(float* d, uint32_t a0, uint32_t a1,
                                        uint32_t a2, uint32_t a3,
                                        uint32_t b0, uint32_t b1) {
    asm volatile(
        "mma.sync.aligned.m16n8k16.row.col.f32.f16.f16.f32 "
        "{%0,%1,%2,%3}, {%4,%5,%6,%7}, {%8,%9}, {%0,%1,%2,%3};"
        : "+f"(d[0]), "+f"(d[1]), "+f"(d[2]), "+f"(d[3])
        : "r"(a0), "r"(a1), "r"(a2), "r"(a3), "r"(b0), "r"(b1));
}

// ---------------------------------------------------------------------------
// K1: leaky integration over T per TC slice + mean over TC.
// ---------------------------------------------------------------------------
__global__ void integrate_kernel(const float* __restrict__ x,
                                 const float* __restrict__ mtc_p,
                                 float* __restrict__ z) {
    int idx = blockIdx.x * blockDim.x + threadIdx.x;
    if (idx >= 4 * 2 * HW) return;
    int p  = idx & (HW - 1);
    int bc = idx >> 14;
    int c  = bc & 1;
    int b  = bc >> 1;

    float mtc = *mtc_p;
    float al[5], om[5];
#pragma unroll
    for (int tc = 0; tc < 5; ++tc) {
        float tau = mtc * exp2f(0.5f * (float)(tc - 2));
        al[tc] = expf(-1.0f / tau);
        om[tc] = 1.0f - al[tc];
    }
    float s[5] = {0.f, 0.f, 0.f, 0.f, 0.f};
    for (int t = 0; t < 16; ++t) {
        float acc = 0.f;
#pragma unroll
        for (int tc = 0; tc < 5; ++tc) {
            float v = x[(size_t)((t * 4 + b) * 10 + tc * 2 + c) * HW + p];
            s[tc] = al[tc] * s[tc] + om[tc] * v;
            acc += s[tc];
        }
        z[(size_t)((t * 4 + b) * 2 + c) * HW + p] = acc * 0.2f;
    }
}

// ---------------------------------------------------------------------------
// K2: head conv 2->16 (FFMA f32x2 path)
// ---------------------------------------------------------------------------
template <int CIN>
__global__ __launch_bounds__(256, 2)
void conv15_to16(const float* __restrict__ in, const float* __restrict__ w,
                 float* __restrict__ out) {
    __shared__ __align__(16) float tile[46 * 48];
    __shared__ __align__(16) float wsm[225 * 16];

    int img = blockIdx.y;
    int bx0 = (blockIdx.x & 3)  * 32;
    int by0 = (blockIdx.x >> 2) * 32;
    int tid = threadIdx.x;
    int tx  = tid & 31;
    int ty  = tid >> 5;

    ull acc[4][8];
#pragma unroll
    for (int r = 0; r < 4; ++r)
#pragma unroll
        for (int j = 0; j < 8; ++j) acc[r][j] = 0ull;

    for (int cin = 0; cin < CIN; ++cin) {
        __syncthreads();
        const float* src = in + ((size_t)img * CIN + cin) * HW;
        for (int i = tid; i < 46 * 46; i += 256) {
            int r  = i / 46, cc = i % 46;
            int gy = by0 + r - 7, gx = bx0 + cc - 7;
            float v = 0.f;
            if (gy >= 0 && gy < 128 && gx >= 0 && gx < 128) v = src[gy * 128 + gx];
            tile[r * 48 + cc] = v;
        }
        for (int i = tid; i < 225 * 16; i += 256) {
            int k = i >> 4, co = i & 15;
            wsm[i] = w[((size_t)co * CIN + cin) * 225 + k];
        }
        __syncthreads();

#pragma unroll 1
        for (int ky = 0; ky < 15; ++ky) {
            const float* trow = &tile[(ty + ky) * 48 + tx];
#pragma unroll
            for (int kx = 0; kx < 15; ++kx) {
                ull p0 = pack2(trow[kx],           trow[kx]);
                ull p1 = pack2(trow[kx +  8 * 48], trow[kx +  8 * 48]);
                ull p2 = pack2(trow[kx + 16 * 48], trow[kx + 16 * 48]);
                ull p3 = pack2(trow[kx + 24 * 48], trow[kx + 24 * 48]);
                const ull* wq = (const ull*)&wsm[(ky * 15 + kx) * 16];
#pragma unroll
                for (int j = 0; j < 8; ++j) {
                    ull wv = wq[j];
                    fma2(acc[0][j], p0, wv);
                    fma2(acc[1][j], p1, wv);
                    fma2(acc[2][j], p2, wv);
                    fma2(acc[3][j], p3, wv);
                }
            }
        }
    }

#pragma unroll
    for (int r = 0; r < 4; ++r) {
        int oy = by0 + ty + 8 * r;
#pragma unroll
        for (int j = 0; j < 8; ++j) {
            float lo, hi;
            unpack2(acc[r][j], lo, hi);
            out[((size_t)img * 16 + 2 * j)     * HW + oy * 128 + bx0 + tx] = lo;
            out[((size_t)img * 16 + 2 * j + 1) * HW + oy * 128 + bx0 + tx] = hi;
        }
    }
}

// ---------------------------------------------------------------------------
// K3a: prepass — each (img,y) row becomes 144 pixel records of 48B:
// [16 fp16 (32B) | 16B pad(0)]. 3-unit stride => conflict-free ldmatrix.
// ---------------------------------------------------------------------------
__global__ __launch_bounds__(160, 4)
void split_rows(const float* __restrict__ in, uint8_t* __restrict__ xs) {
    __shared__ __align__(16) uint8_t rowbuf[144 * 48];
    int y = blockIdx.x, img = blockIdx.y;
    int p = threadIdx.x;

    if (p < 144) {
        int x = p - 7;
        bool valid = (x >= 0 && x < 128);
        __align__(16) __half h[16];
#pragma unroll
        for (int c = 0; c < 16; ++c) {
            float a = valid ? in[((size_t)(img * 16 + c) * 128 + y) * 128 + x] : 0.f;
            h[c] = __float2half_rn(a);
        }
        uint8_t* rb = rowbuf + p * 48;
        *(uint4*)(rb +  0) = *(const uint4*)&h[0];
        *(uint4*)(rb + 16) = *(const uint4*)&h[8];
        *(uint4*)(rb + 32) = make_uint4(0, 0, 0, 0);
    }
    __syncthreads();
    uint8_t* dst = xs + (size_t)(img * 128 + y) * ROWB;
    for (int u = threadIdx.x; u < 432; u += 160)
        *(uint4*)(dst + u * 16) = *(const uint4*)(rowbuf + u * 16);
}

// ---------------------------------------------------------------------------
// K3b: prepass — fp16 weights (x1024 to dodge denormals) into per-(ky,kx)
// 512B blocks: [co 16][cin 16].
// ---------------------------------------------------------------------------
__global__ void split_weights(const float* __restrict__ w, uint8_t* __restrict__ ws) {
    int kxy = blockIdx.x;            // 0..224
    int t   = threadIdx.x;           // 0..255
    int co  = t >> 4, cin = t & 15;
    int ky  = kxy / 15, kx = kxy % 15;
    float wv = w[((size_t)(co * 16 + cin) * 15 + ky) * 15 + kx] * 1024.0f;
    *(__half*)(ws + (size_t)kxy * 512 + co * 32 + cin * 2) = __float2half_rn(wv);
}

// ---------------------------------------------------------------------------
// K4: sq1 conv 16->16 via fp16 HMMA (single-term fp16 x fp16).
// CTA = (image, 4 output rows); 8 warps = (row, x-half), 4 M-tiles each.
// B double-buffered; one barrier per ky. Epilogue scales by 2^-10.
// ---------------------------------------------------------------------------
__global__ __launch_bounds__(256, 1)
void conv_sq1_hmma(const uint8_t* __restrict__ xs, const uint8_t* __restrict__ ws,
                   float* __restrict__ out) {
    extern __shared__ __align__(16) uint8_t sm[];
    uint8_t* Asm = sm;
    uint8_t* Bsm = sm + A_BYTES;     // 2 x B_SLICE

    int tid  = threadIdx.x;
    int lane = tid & 31;
    int w    = tid >> 5;             // warp 0..7
    int r    = w >> 1;               // output row 0..3
    int half = w & 1;                // x half 0..1
    int grp  = blockIdx.x;           // 0..31
    int img  = blockIdx.y;           // 0..63
    int y0   = grp * 4;

    // ---- A ring: 18 input rows (y0-7 .. y0+10), zero-padded at edges ----
    const uint8_t* srcbase = xs + (size_t)img * 128 * ROWB;
    for (int u = tid; u < 18 * 432; u += 256) {
        int slot = u / 432, q = u % 432;
        int yin  = y0 - 7 + slot;
        uint4 v = make_uint4(0, 0, 0, 0);
        if (yin >= 0 && yin < 128)
            v = *(const uint4*)(srcbase + (size_t)yin * ROWB + q * 16);
        *(uint4*)(Asm + slot * ROWB + q * 16) = v;
    }
    // ---- preload B slice ky=0 into buffer 0 ----
    for (int u = tid; u < 480; u += 256)
        *(uint4*)(Bsm + u * 16) = *(const uint4*)(ws + u * 16);

    uint32_t asm_base = smem_u32(Asm);
    uint32_t bsm_base = smem_u32(Bsm);
    int part = lane >> 3, rr = lane & 7;
    uint32_t a_off = (uint32_t)((((part & 1) << 3) + rr) * 48 + ((part >> 1) << 4));
    uint32_t b_off = (uint32_t)((((part >> 1) << 3) + rr) * 32 + ((part & 1) << 4));

    float acc[4][2][4];
#pragma unroll
    for (int t = 0; t < 4; ++t)
#pragma unroll
        for (int h = 0; h < 2; ++h)
#pragma unroll
            for (int i = 0; i < 4; ++i) acc[t][h][i] = 0.f;

    __syncthreads();

#pragma unroll 1
    for (int ky = 0; ky < 15; ++ky) {
        if (ky) __syncthreads();
        if (ky < 14) {                           // prefetch next B slice
            const uint8_t* bw = ws + (size_t)(ky + 1) * B_SLICE;
            uint8_t* bdst = Bsm + ((ky + 1) & 1) * B_SLICE;
            for (int u = tid; u < 480; u += 256)
                *(uint4*)(bdst + u * 16) = *(const uint4*)(bw + u * 16);
        }
        uint32_t bcur = bsm_base + (uint32_t)((ky & 1) * B_SLICE);
        uint32_t arow = asm_base + (uint32_t)((r + ky) * ROWB) + a_off;

#pragma unroll 1
        for (int kx = 0; kx < 15; ++kx) {
            uint32_t b0, b1, b2, b3;
            ldsm4(b0, b1, b2, b3, bcur + kx * 512 + b_off);
            uint32_t abase = arow + kx * 48;
#pragma unroll
            for (int t = 0; t < 4; ++t) {
                int tt = half * 4 + t;           // M-tile 0..7
                uint32_t a0, a1, a2, a3;
                ldsm4(a0, a1, a2, a3, abase + tt * 768);
                mma_f16(acc[t][0], a0, a1, a2, a3, b0, b1);
                mma_f16(acc[t][1], a0, a1, a2, a3, b2, b3);
            }
        }
    }

    // ---- epilogue: scale back 2^-10, stage in smem, coalesced stores ----
    __syncthreads();
    float* stage = (float*)Asm;                  // 32KB needed, fits in A ring
    {
        const float sc = 1.0f / 1024.0f;
        int q  = lane >> 2;
        int cb = (lane & 3) * 2;
#pragma unroll
        for (int t = 0; t < 4; ++t) {
            int tt = half * 4 + t;
            int x  = tt * 16 + q;
#pragma unroll
            for (int h = 0; h < 2; ++h) {
                int co = h * 8 + cb;
                stage[(r * 16 + co)     * 128 + x    ] = acc[t][h][0] * sc;
                stage[(r * 16 + co + 1) * 128 + x    ] = acc[t][h][1] * sc;
                stage[(r * 16 + co)     * 128 + x + 8] = acc[t][h][2] * sc;
                stage[(r * 16 + co + 1) * 128 + x + 8] = acc[t][h][3] * sc;
            }
        }
    }
    __syncthreads();
    for (int i = tid; i < 2048; i += 256) {
        int rw  = i >> 9;
        int rem = i & 511;
        int co  = rem >> 5;
        int x4  = rem & 31;
        float4 v = *(const float4*)&stage[(rw * 16 + co) * 128 + x4 * 4];
        *(float4*)&out[((size_t)(img * 16 + co) * 128 + (y0 + rw)) * 128 + x4 * 4] = v;
    }
}

// ---------------------------------------------------------------------------
// K5: 15x15 conv 16 -> 1 fused with 2x2 max pool. Row-reuse: each thread
// computes 4x * 2y outputs; each loaded row window feeds both y-rows.
// ---------------------------------------------------------------------------
__global__ __launch_bounds__(256, 2)
void conv_sq2_pool(const float* __restrict__ in, const float* __restrict__ w,
                   float* __restrict__ out) {
    __shared__ __align__(16) float tile[78 * 48];
    __shared__ __align__(16) ull  wsm2[225];
    __shared__ float ctile[64 * 32];

    int img = blockIdx.y;
    int bx0 = (blockIdx.x & 3)  * 32;
    int by0 = (blockIdx.x >> 2) * 64;
    int tid = threadIdx.x;
    int tx  = tid & 7;
    int tyg = tid >> 3;

    ull acc[2][2];
    acc[0][0] = acc[0][1] = acc[1][0] = acc[1][1] = 0ull;

    for (int cin = 0; cin < 16; ++cin) {
        __syncthreads();
        const float* src = in + ((size_t)img * 16 + cin) * HW;
        for (int i = tid; i < 78 * 46; i += 256) {
            int rrow = i / 46, cc = i % 46;
            int gy = by0 + rrow - 7, gx = bx0 + cc - 7;
            float v = 0.f;
            if (gy >= 0 && gy < 128 && gx >= 0 && gx < 128) v = src[gy * 128 + gx];
            tile[rrow * 48 + cc] = v;
        }
        if (tid < 225) {
            float wv = w[cin * 225 + tid];
            wsm2[tid] = pack2(wv, wv);
        }
        __syncthreads();

#pragma unroll 1
        for (int s = 0; s < 16; ++s) {
            int trow = tyg * 2 + s;
            const float4* tp = (const float4*)&tile[trow * 48 + 4 * tx];
            float4 v0 = tp[0], v1 = tp[1], v2 = tp[2], v3 = tp[3], v4 = tp[4];
            float rv[20] = {v0.x, v0.y, v0.z, v0.w, v1.x, v1.y, v1.z, v1.w,
                            v2.x, v2.y, v2.z, v2.w, v3.x, v3.y, v3.z, v3.w,
                            v4.x, v4.y, v4.z, v4.w};
            ull pr[17];
#pragma unroll
            for (int k = 0; k < 17; ++k) pr[k] = pack2(rv[k], rv[k + 1]);
            if (s < 15) {
                const ull* wrow = &wsm2[s * 15];
#pragma unroll
                for (int kx = 0; kx < 15; ++kx) {
                    ull wv = wrow[kx];
                    fma2(acc[0][0], pr[kx],     wv);
                    fma2(acc[0][1], pr[kx + 2], wv);
                }
            }
            if (s >= 1) {
                const ull* wrow = &wsm2[(s - 1) * 15];
#pragma unroll
                for (int kx = 0; kx < 15; ++kx) {
                    ull wv = wrow[kx];
                    fma2(acc[1][0], pr[kx],     wv);
                    fma2(acc[1][1], pr[kx + 2], wv);
                }
            }
        }
    }

    __syncthreads();
#pragma unroll
    for (int r = 0; r < 2; ++r) {
        float o0, o1, o2, o3;
        unpack2(acc[r][0], o0, o1);
        unpack2(acc[r][1], o2, o3);
        float* cr = &ctile[(tyg * 2 + r) * 32 + 4 * tx];
        cr[0] = o0; cr[1] = o1; cr[2] = o2; cr[3] = o3;
    }
    __syncthreads();

    int px = tid & 15, py0 = tid >> 4;
#pragma unroll
    for (int hh = 0; hh < 2; ++hh) {
        int py = py0 + hh * 16;
        float m = fmaxf(fmaxf(ctile[(2 * py) * 32 + 2 * px],     ctile[(2 * py) * 32 + 2 * px + 1]),
                        fmaxf(ctile[(2 * py + 1) * 32 + 2 * px], ctile[(2 * py + 1) * 32 + 2 * px + 1]));
        out[(size_t)img * 4096 + (by0 / 2 + py) * 64 + (bx0 / 2 + px)] = m;
    }
}

// ---------------------------------------------------------------------------
// K6: softmax over 64x64 heatmap + soft-argmax. One block per image.
// ---------------------------------------------------------------------------
__global__ void softargmax_kernel(const float* __restrict__ heat,
                                  float* __restrict__ coords) {
    __shared__ float red[256];
    int img = blockIdx.x, tid = threadIdx.x;
    const float* h = heat + (size_t)img * 4096;

    float v[16];
    float m = -1e30f;
#pragma unroll
    for (int i = 0; i < 16; ++i) { v[i] = h[tid + 256 * i]; m = fmaxf(m, v[i]); }

    red[tid] = m; __syncthreads();
    for (int s = 128; s > 0; s >>= 1) {
        if (tid < s) red[tid] = fmaxf(red[tid], red[tid + s]);
        __syncthreads();
    }
    m = red[0]; __syncthreads();

    float se = 0.f, sx = 0.f, sy = 0.f;
#pragma unroll
    for (int i = 0; i < 16; ++i) {
        int k = tid + 256 * i;
        float e = expf(v[i] - m);
        se += e;
        sx += e * (float)(k & 63);
        sy += e * (float)(k >> 6);
    }

    red[tid] = se; __syncthreads();
    for (int s = 128; s > 0; s >>= 1) { if (tid < s) red[tid] += red[tid + s]; __syncthreads(); }
    float tot = red[0]; __syncthreads();

    red[tid] = sx; __syncthreads();
    for (int s = 128; s > 0; s >>= 1) { if (tid < s) red[tid] += red[tid + s]; __syncthreads(); }
    float totx = red[0]; __syncthreads();

    red[tid] = sy; __syncthreads();
    for (int s = 128; s > 0; s >>= 1) { if (tid < s) red[tid] += red[tid + s]; __syncthreads(); }
    float toty = red[0];

    if (tid == 0) {
        coords[img * 2 + 0] = totx / (63.0f * tot);
        coords[img * 2 + 1] = toty / (63.0f * tot);
    }
}

// ---------------------------------------------------------------------------
extern "C" void kernel_launch(void* const* d_in, const int* in_sizes, int n_in,
                              void* d_out, int out_size) {
    const float* x      = (const float*)d_in[0];
    const float* head_w = (const float*)d_in[1];
    const float* sq1_w  = (const float*)d_in[2];
    const float* sq2_w  = (const float*)d_in[3];
    const float* mtc    = (const float*)d_in[4];
    float* out = (float*)d_out;

    float *zp, *xmp, *h1p;
    uint8_t *xsp, *wsp;
    cudaGetSymbolAddress((void**)&zp,  g_z);
    cudaGetSymbolAddress((void**)&xmp, g_xm);
    cudaGetSymbolAddress((void**)&h1p, g_h1);
    cudaGetSymbolAddress((void**)&xsp, g_xs);
    cudaGetSymbolAddress((void**)&wsp, g_ws);

    cudaFuncSetAttribute(conv_sq1_hmma,
                         cudaFuncAttributeMaxDynamicSharedMemorySize, SQ1_SMEM);

    integrate_kernel<<<512, 256>>>(x, mtc, zp);
    split_weights<<<225, 256>>>(sq1_w, wsp);
    conv15_to16<2><<<dim3(16, NIMG), 256>>>(zp, head_w, xmp);
    split_rows<<<dim3(128, NIMG), 160>>>(xmp, xsp);
    conv_sq1_hmma<<<dim3(32, NIMG), 256, SQ1_SMEM>>>(xsp, wsp, h1p);
    conv_sq2_pool<<<dim3(8, NIMG), 256>>>(h1p, sq2_w, out);

    if (out_size >= NIMG * 4096 + NIMG * 2) {
        softargmax_kernel<<<NIMG, 256>>>(out, out + (size_t)NIMG * 4096);
    }
}

// round 9
// speedup vs baseline: 2.8518x; 1.0053x over previous
#include <cuda_runtime.h>
#include <cuda_bf16.h>
#include <cuda_fp16.h>
#include <math.h>
#include <stdint.h>

#define NIMG 64          // T*B = 16*4
#define HW   16384       // 128*128
typedef unsigned long long ull;

// Scratch (allocation-free rule: __device__ globals)
__device__ float   g_z [NIMG *  2 * HW];                 //  8 MB integrated input
__device__ float   g_xm[NIMG * 16 * HW];                 // 64 MB head conv output
__device__ float   g_h1[NIMG * 16 * HW];                 // 64 MB sq1 conv output
__device__ uint8_t g_xs[(size_t)NIMG * 128 * 144 * 48];  // 56.6 MB fp16 pixel rows
__device__ uint8_t g_ws[225 * 768];                      // fp16 weights (x1024), 48B rows

#define ROWB 6912                        // 144 px * 48 B
#define A_BYTES (18 * ROWB)              // 124416
#define B_SLICE 11520                    // 15 kx * 768
#define SQ1_SMEM (A_BYTES + 2 * B_SLICE) // 147456 (B double-buffered)

// ---- f32x2 helpers --------------------------------------------------------
__device__ __forceinline__ void fma2(ull& d, ull a, ull b) {
    asm("fma.rn.f32x2 %0, %1, %2, %0;" : "+l"(d) : "l"(a), "l"(b));
}
__device__ __forceinline__ ull pack2(float lo, float hi) {
    ull r; asm("mov.b64 %0, {%1, %2};" : "=l"(r) : "f"(lo), "f"(hi)); return r;
}
__device__ __forceinline__ void unpack2(ull v, float& lo, float& hi) {
    asm("mov.b64 {%0, %1}, %2;" : "=f"(lo), "=f"(hi) : "l"(v));
}

// ---- HMMA helpers ---------------------------------------------------------
__device__ __forceinline__ uint32_t smem_u32(const void* p) {
    uint32_t a;
    asm("{ .reg .u64 t; cvta.to.shared.u64 t, %1; cvt.u32.u64 %0, t; }" : "=r"(a) : "l"(p));
    return a;
}
__device__ __forceinline__ void ldsm4(uint32_t* r, uint32_t a) {
    asm volatile("ldmatrix.sync.aligned.m8n8.x4.shared.b16 {%0,%1,%2,%3}, [%4];"
                 : "=r"(r[0]), "=r"(r[1]), "=r"(r[2]), "=r"(r[3]) : "r"(a));
}
__device__ __forceinline__ void mma_f16(float* d, const uint32_t* a,
                                        uint32_t b0, uint32_t b1) {
    asm volatile(
        "mma.sync.aligned.m16n8k16.row.col.f32.f16.f16.f32 "
        "{%0,%1,%2,%3}, {%4,%5,%6,%7}, {%8,%9}, {%0,%1,%2,%3};"
        : "+f"(d[0]), "+f"(d[1]), "+f"(d[2]), "+f"(d[3])
        : "r"(a[0]), "r"(a[1]), "r"(a[2]), "r"(a[3]), "r"(b0), "r"(b1));
}

// ---------------------------------------------------------------------------
// K1: leaky integration over T per TC slice + mean over TC.
// ---------------------------------------------------------------------------
__global__ void integrate_kernel(const float* __restrict__ x,
                                 const float* __restrict__ mtc_p,
                                 float* __restrict__ z) {
    int idx = blockIdx.x * blockDim.x + threadIdx.x;
    if (idx >= 4 * 2 * HW) return;
    int p  = idx & (HW - 1);
    int bc = idx >> 14;
    int c  = bc & 1;
    int b  = bc >> 1;

    float mtc = *mtc_p;
    float al[5], om[5];
#pragma unroll
    for (int tc = 0; tc < 5; ++tc) {
        float tau = mtc * exp2f(0.5f * (float)(tc - 2));
        al[tc] = expf(-1.0f / tau);
        om[tc] = 1.0f - al[tc];
    }
    float s[5] = {0.f, 0.f, 0.f, 0.f, 0.f};
    for (int t = 0; t < 16; ++t) {
        float acc = 0.f;
#pragma unroll
        for (int tc = 0; tc < 5; ++tc) {
            float v = x[(size_t)((t * 4 + b) * 10 + tc * 2 + c) * HW + p];
            s[tc] = al[tc] * s[tc] + om[tc] * v;
            acc += s[tc];
        }
        z[(size_t)((t * 4 + b) * 2 + c) * HW + p] = acc * 0.2f;
    }
}

// ---------------------------------------------------------------------------
// K2: head conv 2->16 (FFMA f32x2 path)
// ---------------------------------------------------------------------------
template <int CIN>
__global__ __launch_bounds__(256, 2)
void conv15_to16(const float* __restrict__ in, const float* __restrict__ w,
                 float* __restrict__ out) {
    __shared__ __align__(16) float tile[46 * 48];
    __shared__ __align__(16) float wsm[225 * 16];

    int img = blockIdx.y;
    int bx0 = (blockIdx.x & 3)  * 32;
    int by0 = (blockIdx.x >> 2) * 32;
    int tid = threadIdx.x;
    int tx  = tid & 31;
    int ty  = tid >> 5;

    ull acc[4][8];
#pragma unroll
    for (int r = 0; r < 4; ++r)
#pragma unroll
        for (int j = 0; j < 8; ++j) acc[r][j] = 0ull;

    for (int cin = 0; cin < CIN; ++cin) {
        __syncthreads();
        const float* src = in + ((size_t)img * CIN + cin) * HW;
        for (int i = tid; i < 46 * 46; i += 256) {
            int r  = i / 46, cc = i % 46;
            int gy = by0 + r - 7, gx = bx0 + cc - 7;
            float v = 0.f;
            if (gy >= 0 && gy < 128 && gx >= 0 && gx < 128) v = src[gy * 128 + gx];
            tile[r * 48 + cc] = v;
        }
        for (int i = tid; i < 225 * 16; i += 256) {
            int k = i >> 4, co = i & 15;
            wsm[i] = w[((size_t)co * CIN + cin) * 225 + k];
        }
        __syncthreads();

#pragma unroll 1
        for (int ky = 0; ky < 15; ++ky) {
            const float* trow = &tile[(ty + ky) * 48 + tx];
#pragma unroll
            for (int kx = 0; kx < 15; ++kx) {
                ull p0 = pack2(trow[kx],           trow[kx]);
                ull p1 = pack2(trow[kx +  8 * 48], trow[kx +  8 * 48]);
                ull p2 = pack2(trow[kx + 16 * 48], trow[kx + 16 * 48]);
                ull p3 = pack2(trow[kx + 24 * 48], trow[kx + 24 * 48]);
                const ull* wq = (const ull*)&wsm[(ky * 15 + kx) * 16];
#pragma unroll
                for (int j = 0; j < 8; ++j) {
                    ull wv = wq[j];
                    fma2(acc[0][j], p0, wv);
                    fma2(acc[1][j], p1, wv);
                    fma2(acc[2][j], p2, wv);
                    fma2(acc[3][j], p3, wv);
                }
            }
        }
    }

#pragma unroll
    for (int r = 0; r < 4; ++r) {
        int oy = by0 + ty + 8 * r;
#pragma unroll
        for (int j = 0; j < 8; ++j) {
            float lo, hi;
            unpack2(acc[r][j], lo, hi);
            out[((size_t)img * 16 + 2 * j)     * HW + oy * 128 + bx0 + tx] = lo;
            out[((size_t)img * 16 + 2 * j + 1) * HW + oy * 128 + bx0 + tx] = hi;
        }
    }
}

// ---------------------------------------------------------------------------
// K3a: prepass — each (img,y) row becomes 144 pixel records of 48B:
// [16 fp16 (32B) | 16B pad(0)]. 3-unit stride => conflict-free ldmatrix.
// ---------------------------------------------------------------------------
__global__ __launch_bounds__(160, 4)
void split_rows(const float* __restrict__ in, uint8_t* __restrict__ xs) {
    __shared__ __align__(16) uint8_t rowbuf[144 * 48];
    int y = blockIdx.x, img = blockIdx.y;
    int p = threadIdx.x;

    if (p < 144) {
        int x = p - 7;
        bool valid = (x >= 0 && x < 128);
        __align__(16) __half h[16];
#pragma unroll
        for (int c = 0; c < 16; ++c) {
            float a = valid ? in[((size_t)(img * 16 + c) * 128 + y) * 128 + x] : 0.f;
            h[c] = __float2half_rn(a);
        }
        uint8_t* rb = rowbuf + p * 48;
        *(uint4*)(rb +  0) = *(const uint4*)&h[0];
        *(uint4*)(rb + 16) = *(const uint4*)&h[8];
        *(uint4*)(rb + 32) = make_uint4(0, 0, 0, 0);
    }
    __syncthreads();
    uint8_t* dst = xs + (size_t)(img * 128 + y) * ROWB;
    for (int u = threadIdx.x; u < 432; u += 160)
        *(uint4*)(dst + u * 16) = *(const uint4*)(rowbuf + u * 16);
}

// ---------------------------------------------------------------------------
// K3b: prepass — fp16 weights (x1024 to dodge denormals) into per-(ky,kx)
// 768B blocks: [co 16 rows x 48B stride], 2B halves at cin*2. Conflict-free.
// ---------------------------------------------------------------------------
__global__ void split_weights(const float* __restrict__ w, uint8_t* __restrict__ ws) {
    int kxy = blockIdx.x;            // 0..224
    int t   = threadIdx.x;           // 0..255
    int co  = t >> 4, cin = t & 15;
    int ky  = kxy / 15, kx = kxy % 15;
    float wv = w[((size_t)(co * 16 + cin) * 15 + ky) * 15 + kx] * 1024.0f;
    uint8_t* blk = ws + (size_t)kxy * 768;
    *(__half*)(blk + co * 48 + cin * 2) = __float2half_rn(wv);
    if (cin == 0) *(uint4*)(blk + co * 48 + 32) = make_uint4(0, 0, 0, 0); // pad
}

// ---------------------------------------------------------------------------
// K4: sq1 conv 16->16 via fp16 HMMA, software-pipelined kx loop.
// CTA = (image, 4 output rows); 8 warps = (row, x-half), 4 M-tiles each.
// B double-buffered in smem; fragment double-buffer in registers.
// ---------------------------------------------------------------------------
__global__ __launch_bounds__(256, 1)
void conv_sq1_hmma(const uint8_t* __restrict__ xs, const uint8_t* __restrict__ ws,
                   float* __restrict__ out) {
    extern __shared__ __align__(16) uint8_t sm[];
    uint8_t* Asm = sm;
    uint8_t* Bsm = sm + A_BYTES;     // 2 x B_SLICE

    int tid  = threadIdx.x;
    int lane = tid & 31;
    int w    = tid >> 5;             // warp 0..7
    int r    = w >> 1;               // output row 0..3
    int half = w & 1;                // x half 0..1
    int grp  = blockIdx.x;           // 0..31
    int img  = blockIdx.y;           // 0..63
    int y0   = grp * 4;

    // ---- A ring: 18 input rows (y0-7 .. y0+10), zero-padded at edges ----
    const uint8_t* srcbase = xs + (size_t)img * 128 * ROWB;
    for (int u = tid; u < 18 * 432; u += 256) {
        int slot = u / 432, q = u % 432;
        int yin  = y0 - 7 + slot;
        uint4 v = make_uint4(0, 0, 0, 0);
        if (yin >= 0 && yin < 128)
            v = *(const uint4*)(srcbase + (size_t)yin * ROWB + q * 16);
        *(uint4*)(Asm + slot * ROWB + q * 16) = v;
    }
    // ---- preload B slice ky=0 into buffer 0 ----
    for (int u = tid; u < 720; u += 256)
        *(uint4*)(Bsm + u * 16) = *(const uint4*)(ws + u * 16);

    uint32_t asm_base = smem_u32(Asm);
    uint32_t bsm_base = smem_u32(Bsm);
    int part = lane >> 3, rr = lane & 7;
    uint32_t a_off = (uint32_t)((((part & 1) << 3) + rr) * 48 + ((part >> 1) << 4));
    uint32_t b_off = (uint32_t)((((part >> 1) << 3) + rr) * 48 + ((part & 1) << 4));

    float acc[4][2][4];
#pragma unroll
    for (int t = 0; t < 4; ++t)
#pragma unroll
        for (int h = 0; h < 2; ++h)
#pragma unroll
            for (int i = 0; i < 4; ++i) acc[t][h][i] = 0.f;

    __syncthreads();

#pragma unroll 1
    for (int ky = 0; ky < 15; ++ky) {
        if (ky) __syncthreads();
        if (ky < 14) {                           // prefetch next B slice (gmem)
            const uint8_t* bw = ws + (size_t)(ky + 1) * B_SLICE;
            uint8_t* bdst = Bsm + ((ky + 1) & 1) * B_SLICE;
            for (int u = tid; u < 720; u += 256)
                *(uint4*)(bdst + u * 16) = *(const uint4*)(bw + u * 16);
        }
        uint32_t bcur = bsm_base + (uint32_t)((ky & 1) * B_SLICE) + b_off;
        uint32_t arow = asm_base + (uint32_t)((r + ky) * ROWB) + a_off
                      + (uint32_t)(half * 4 * 768);

        // ---- software-pipelined kx loop: double-buffered fragments ----
        uint32_t B[2][4], A[2][4][4];
        ldsm4(B[0], bcur);
#pragma unroll
        for (int t = 0; t < 4; ++t) ldsm4(A[0][t], arow + t * 768);

#pragma unroll
        for (int kx = 0; kx < 15; ++kx) {
            int cur = kx & 1, nxt = cur ^ 1;
            if (kx < 14) {
                ldsm4(B[nxt], bcur + (kx + 1) * 768);
                uint32_t an = arow + (kx + 1) * 48;
#pragma unroll
                for (int t = 0; t < 4; ++t) ldsm4(A[nxt][t], an + t * 768);
            }
#pragma unroll
            for (int t = 0; t < 4; ++t) {
                mma_f16(acc[t][0], A[cur][t], B[cur][0], B[cur][1]);
                mma_f16(acc[t][1], A[cur][t], B[cur][2], B[cur][3]);
            }
        }
    }

    // ---- epilogue: scale back 2^-10, stage in smem, coalesced stores ----
    __syncthreads();
    float* stage = (float*)Asm;                  // 32KB needed, fits in A ring
    {
        const float sc = 1.0f / 1024.0f;
        int q  = lane >> 2;
        int cb = (lane & 3) * 2;
#pragma unroll
        for (int t = 0; t < 4; ++t) {
            int tt = half * 4 + t;
            int x  = tt * 16 + q;
#pragma unroll
            for (int h = 0; h < 2; ++h) {
                int co = h * 8 + cb;
                stage[(r * 16 + co)     * 128 + x    ] = acc[t][h][0] * sc;
                stage[(r * 16 + co + 1) * 128 + x    ] = acc[t][h][1] * sc;
                stage[(r * 16 + co)     * 128 + x + 8] = acc[t][h][2] * sc;
                stage[(r * 16 + co + 1) * 128 + x + 8] = acc[t][h][3] * sc;
            }
        }
    }
    __syncthreads();
    for (int i = tid; i < 2048; i += 256) {
        int rw  = i >> 9;
        int rem = i & 511;
        int co  = rem >> 5;
        int x4  = rem & 31;
        float4 v = *(const float4*)&stage[(rw * 16 + co) * 128 + x4 * 4];
        *(float4*)&out[((size_t)(img * 16 + co) * 128 + (y0 + rw)) * 128 + x4 * 4] = v;
    }
}

// ---------------------------------------------------------------------------
// K5: 15x15 conv 16 -> 1 fused with 2x2 max pool. Row-reuse: each thread
// computes 4x * 2y outputs; each loaded row window feeds both y-rows.
// ---------------------------------------------------------------------------
__global__ __launch_bounds__(256, 2)
void conv_sq2_pool(const float* __restrict__ in, const float* __restrict__ w,
                   float* __restrict__ out) {
    __shared__ __align__(16) float tile[78 * 48];
    __shared__ __align__(16) ull  wsm2[225];
    __shared__ float ctile[64 * 32];

    int img = blockIdx.y;
    int bx0 = (blockIdx.x & 3)  * 32;
    int by0 = (blockIdx.x >> 2) * 64;
    int tid = threadIdx.x;
    int tx  = tid & 7;
    int tyg = tid >> 3;

    ull acc[2][2];
    acc[0][0] = acc[0][1] = acc[1][0] = acc[1][1] = 0ull;

    for (int cin = 0; cin < 16; ++cin) {
        __syncthreads();
        const float* src = in + ((size_t)img * 16 + cin) * HW;
        for (int i = tid; i < 78 * 46; i += 256) {
            int rrow = i / 46, cc = i % 46;
            int gy = by0 + rrow - 7, gx = bx0 + cc - 7;
            float v = 0.f;
            if (gy >= 0 && gy < 128 && gx >= 0 && gx < 128) v = src[gy * 128 + gx];
            tile[rrow * 48 + cc] = v;
        }
        if (tid < 225) {
            float wv = w[cin * 225 + tid];
            wsm2[tid] = pack2(wv, wv);
        }
        __syncthreads();

#pragma unroll 1
        for (int s = 0; s < 16; ++s) {
            int trow = tyg * 2 + s;
            const float4* tp = (const float4*)&tile[trow * 48 + 4 * tx];
            float4 v0 = tp[0], v1 = tp[1], v2 = tp[2], v3 = tp[3], v4 = tp[4];
            float rv[20] = {v0.x, v0.y, v0.z, v0.w, v1.x, v1.y, v1.z, v1.w,
                            v2.x, v2.y, v2.z, v2.w, v3.x, v3.y, v3.z, v3.w,
                            v4.x, v4.y, v4.z, v4.w};
            ull pr[17];
#pragma unroll
            for (int k = 0; k < 17; ++k) pr[k] = pack2(rv[k], rv[k + 1]);
            if (s < 15) {
                const ull* wrow = &wsm2[s * 15];
#pragma unroll
                for (int kx = 0; kx < 15; ++kx) {
                    ull wv = wrow[kx];
                    fma2(acc[0][0], pr[kx],     wv);
                    fma2(acc[0][1], pr[kx + 2], wv);
                }
            }
            if (s >= 1) {
                const ull* wrow = &wsm2[(s - 1) * 15];
#pragma unroll
                for (int kx = 0; kx < 15; ++kx) {
                    ull wv = wrow[kx];
                    fma2(acc[1][0], pr[kx],     wv);
                    fma2(acc[1][1], pr[kx + 2], wv);
                }
            }
        }
    }

    __syncthreads();
#pragma unroll
    for (int r = 0; r < 2; ++r) {
        float o0, o1, o2, o3;
        unpack2(acc[r][0], o0, o1);
        unpack2(acc[r][1], o2, o3);
        float* cr = &ctile[(tyg * 2 + r) * 32 + 4 * tx];
        cr[0] = o0; cr[1] = o1; cr[2] = o2; cr[3] = o3;
    }
    __syncthreads();

    int px = tid & 15, py0 = tid >> 4;
#pragma unroll
    for (int hh = 0; hh < 2; ++hh) {
        int py = py0 + hh * 16;
        float m = fmaxf(fmaxf(ctile[(2 * py) * 32 + 2 * px],     ctile[(2 * py) * 32 + 2 * px + 1]),
                        fmaxf(ctile[(2 * py + 1) * 32 + 2 * px], ctile[(2 * py + 1) * 32 + 2 * px + 1]));
        out[(size_t)img * 4096 + (by0 / 2 + py) * 64 + (bx0 / 2 + px)] = m;
    }
}

// ---------------------------------------------------------------------------
// K6: softmax over 64x64 heatmap + soft-argmax. One block per image.
// ---------------------------------------------------------------------------
__global__ void softargmax_kernel(const float* __restrict__ heat,
                                  float* __restrict__ coords) {
    __shared__ float red[256];
    int img = blockIdx.x, tid = threadIdx.x;
    const float* h = heat + (size_t)img * 4096;

    float v[16];
    float m = -1e30f;
#pragma unroll
    for (int i = 0; i < 16; ++i) { v[i] = h[tid + 256 * i]; m = fmaxf(m, v[i]); }

    red[tid] = m; __syncthreads();
    for (int s = 128; s > 0; s >>= 1) {
        if (tid < s) red[tid] = fmaxf(red[tid], red[tid + s]);
        __syncthreads();
    }
    m = red[0]; __syncthreads();

    float se = 0.f, sx = 0.f, sy = 0.f;
#pragma unroll
    for (int i = 0; i < 16; ++i) {
        int k = tid + 256 * i;
        float e = expf(v[i] - m);
        se += e;
        sx += e * (float)(k & 63);
        sy += e * (float)(k >> 6);
    }

    red[tid] = se; __syncthreads();
    for (int s = 128; s > 0; s >>= 1) { if (tid < s) red[tid] += red[tid + s]; __syncthreads(); }
    float tot = red[0]; __syncthreads();

    red[tid] = sx; __syncthreads();
    for (int s = 128; s > 0; s >>= 1) { if (tid < s) red[tid] += red[tid + s]; __syncthreads(); }
    float totx = red[0]; __syncthreads();

    red[tid] = sy; __syncthreads();
    for (int s = 128; s > 0; s >>= 1) { if (tid < s) red[tid] += red[tid + s]; __syncthreads(); }
    float toty = red[0];

    if (tid == 0) {
        coords[img * 2 + 0] = totx / (63.0f * tot);
        coords[img * 2 + 1] = toty / (63.0f * tot);
    }
}

// ---------------------------------------------------------------------------
extern "C" void kernel_launch(void* const* d_in, const int* in_sizes, int n_in,
                              void* d_out, int out_size) {
    const float* x      = (const float*)d_in[0];
    const float* head_w = (const float*)d_in[1];
    const float* sq1_w  = (const float*)d_in[2];
    const float* sq2_w  = (const float*)d_in[3];
    const float* mtc    = (const float*)d_in[4];
    float* out = (float*)d_out;

    float *zp, *xmp, *h1p;
    uint8_t *xsp, *wsp;
    cudaGetSymbolAddress((void**)&zp,  g_z);
    cudaGetSymbolAddress((void**)&xmp, g_xm);
    cudaGetSymbolAddress((void**)&h1p, g_h1);
    cudaGetSymbolAddress((void**)&xsp, g_xs);
    cudaGetSymbolAddress((void**)&wsp, g_ws);

    cudaFuncSetAttribute(conv_sq1_hmma,
                         cudaFuncAttributeMaxDynamicSharedMemorySize, SQ1_SMEM);

    integrate_kernel<<<512, 256>>>(x, mtc, zp);
    split_weights<<<225, 256>>>(sq1_w, wsp);
    conv15_to16<2><<<dim3(16, NIMG), 256>>>(zp, head_w, xmp);
    split_rows<<<dim3(128, NIMG), 160>>>(xmp, xsp);
    conv_sq1_hmma<<<dim3(32, NIMG), 256, SQ1_SMEM>>>(xsp, wsp, h1p);
    conv_sq2_pool<<<dim3(8, NIMG), 256>>>(h1p, sq2_w, out);

    if (out_size >= NIMG * 4096 + NIMG * 2) {
        softargmax_kernel<<<NIMG, 256>>>(out, out + (size_t)NIMG * 4096);
    }
}